// round 13
// baseline (speedup 1.0000x reference)
#include <cuda_runtime.h>
#include <cuda_bf16.h>
#include <cstdint>
#include <math.h>

// ---------------- problem constants ----------------
#define BATCH     2
#define TQ        197
#define DIMM      256
#define HEADS     4
#define DH        64
#define FIVE      1280
#define MLPD      1024
#define NCLS      1000
#define PATCH_DIM 768
#define NPATCH    196
#define MROWS     (BATCH*TQ)     // 394

// ---------------- tritt v7 constants ----------------
#define TT_THREADS 256
#define MPAD       224           // 7 warps x 32 rows
#define BROWS      208
#define QB         4
#define NQCHUNK    50            // ceil(197/4)
#define PADC       11.0f         // pad cols per valid row (208-197)
#define PADR       27.0f         // pad rows per valid col (224-197)
#define ZCORR      (197.0f*PADC) // 2167

// dynamic smem byte offsets (A/B 1024-aligned for swizzle)
#define SMB_RED    0                        // 32 floats (8 used)
#define SMB_CVEC4  256                      // 4*64 floats
#define SMB_ROWM4  1280                     // 4*208 floats
#define SMB_COLM4  4608                     // 4*208 floats
#define SMB_A      8192                     // 224 x 128B bf16 swizzled
#define SMB_B      (SMB_A + MPAD*128)       // 36864: 208 x 128B
#define SMB_TOTAL  (SMB_B + BROWS*128)      // 63488 bytes

__device__ __forceinline__ uint32_t swz(uint32_t off) {
    return off ^ ((off >> 3) & 0x70);
}

// ---------------- device scratch ----------------
__device__ float g_pn[BATCH*NPATCH*PATCH_DIM];
__device__ float g_x[MROWS*DIMM];
__device__ float g_xn[MROWS*DIMM];
__device__ float g_ab[MROWS*FIVE];
__device__ float g_z[MROWS*DIMM];
__device__ float g_h[MROWS*MLPD];
__device__ float g_part[4*MROWS*DIMM];   // split-K partials (max 4 slabs)

// ---------------- PTX helpers ----------------
__device__ __forceinline__ uint32_t smem_u32(const void* p) {
    uint32_t a;
    asm("{ .reg .u64 t; cvta.to.shared.u64 t, %1; cvt.u32.u64 %0, t; }" : "=r"(a) : "l"(p));
    return a;
}
__device__ __forceinline__ void ldm_x4(uint32_t addr, uint32_t* r) {
    asm volatile("ldmatrix.sync.aligned.m8n8.x4.shared.b16 {%0,%1,%2,%3}, [%4];"
                 : "=r"(r[0]), "=r"(r[1]), "=r"(r[2]), "=r"(r[3]) : "r"(addr));
}
__device__ __forceinline__ void ldm_x2(uint32_t addr, uint32_t* r) {
    asm volatile("ldmatrix.sync.aligned.m8n8.x2.shared.b16 {%0,%1}, [%2];"
                 : "=r"(r[0]), "=r"(r[1]) : "r"(addr));
}
__device__ __forceinline__ void mma16816(float* c, const uint32_t* a, const uint32_t* b) {
    asm volatile("mma.sync.aligned.m16n8k16.row.col.f32.bf16.bf16.f32 "
                 "{%0,%1,%2,%3}, {%4,%5,%6,%7}, {%8,%9}, {%0,%1,%2,%3};"
                 : "+f"(c[0]), "+f"(c[1]), "+f"(c[2]), "+f"(c[3])
                 : "r"(a[0]), "r"(a[1]), "r"(a[2]), "r"(a[3]), "r"(b[0]), "r"(b[1]));
}
__device__ __forceinline__ uint32_t hmul2u(uint32_t a, uint32_t b) {
    __nv_bfloat162 x = *(__nv_bfloat162*)&a, y = *(__nv_bfloat162*)&b;
    __nv_bfloat162 z = __hmul2(x, y);
    return *(uint32_t*)&z;
}
// cp.async helpers (sm_80+ portable)
__device__ __forceinline__ void cp16(uint32_t smem, const void* g, bool pred) {
    int sz = pred ? 16 : 0;
    asm volatile("cp.async.cg.shared.global [%0], [%1], 16, %2;"
                 :: "r"(smem), "l"(g), "r"(sz));
}
__device__ __forceinline__ void cp_commit() {
    asm volatile("cp.async.commit_group;" ::: "memory");
}
template<int N>
__device__ __forceinline__ void cp_wait() {
    asm volatile("cp.async.wait_group %0;" :: "n"(N) : "memory");
}

// ---------------- reductions (blockDim == 256, 8 warps) ----------------
__device__ __forceinline__ float block_reduce_sum(float v, float* red) {
    #pragma unroll
    for (int o = 16; o > 0; o >>= 1) v += __shfl_xor_sync(0xffffffffu, v, o);
    if ((threadIdx.x & 31) == 0) red[threadIdx.x >> 5] = v;
    __syncthreads();
    if (threadIdx.x < 32) {
        float r = (threadIdx.x < 8) ? red[threadIdx.x] : 0.f;
        #pragma unroll
        for (int o = 4; o > 0; o >>= 1) r += __shfl_xor_sync(0xffffffffu, r, o);
        if (threadIdx.x == 0) red[0] = r;
    }
    __syncthreads();
    float out = red[0];
    __syncthreads();
    return out;
}

// ---------------- fused patch gather + LN1 ----------------
__global__ void gather_ln_kernel(const float* __restrict__ img,
                                 const float* __restrict__ g, const float* __restrict__ bv) {
    __shared__ float red[32];
    int row = blockIdx.x;
    int b = row / NPATCH, pidx = row % NPATCH;
    int gh = pidx / 14, gw = pidx % 14;
    float v[3];
    #pragma unroll
    for (int r = 0; r < 3; r++) {
        int j = threadIdx.x + r*256;
        int p1 = j / 48, rem = j % 48, p2 = rem / 3, c = rem % 3;
        v[r] = img[(((size_t)b*3 + c)*224 + gh*16 + p1)*224 + gw*16 + p2];
    }
    float s = v[0] + v[1] + v[2];
    float mean = block_reduce_sum(s, red) * (1.f/PATCH_DIM);
    float vs = 0.f;
    #pragma unroll
    for (int r = 0; r < 3; r++) { float d = v[r]-mean; vs += d*d; }
    float var = block_reduce_sum(vs, red) * (1.f/PATCH_DIM);
    float inv = rsqrtf(var + 1e-5f);
    #pragma unroll
    for (int r = 0; r < 3; r++) {
        int j = threadIdx.x + r*256;
        g_pn[(size_t)row*PATCH_DIM + j] = (v[r]-mean)*inv*g[j] + bv[j];
    }
}

// ---------------- fused assemble: patch combine + LN2 + cls/pos + attn LN0 ----------------
__global__ void assemble_fused_kernel(const float* __restrict__ P,
                                      const float* __restrict__ pbias,
                                      const float* __restrict__ g2, const float* __restrict__ b2,
                                      const float* __restrict__ cls, const float* __restrict__ pos,
                                      const float* __restrict__ ga, const float* __restrict__ ba,
                                      float* __restrict__ X, float* __restrict__ XN) {
    __shared__ float red[32];
    int row = blockIdx.x;
    int b = row / TQ, t = row % TQ;
    int j = threadIdx.x;
    float xv;
    if (t == 0) {
        xv = cls[j] + pos[j];
    } else {
        int prow = b*NPATCH + t - 1;
        float v = pbias[j];
        #pragma unroll
        for (int s = 0; s < 3; s++)
            v += P[(size_t)s*BATCH*NPATCH*DIMM + (size_t)prow*DIMM + j];
        float mean = block_reduce_sum(v, red) * (1.f/DIMM);
        float d = v - mean;
        float var = block_reduce_sum(d*d, red) * (1.f/DIMM);
        float inv = rsqrtf(var + 1e-5f);
        xv = d*inv*g2[j] + b2[j] + pos[t*DIMM + j];
    }
    X[(size_t)row*DIMM + j] = xv;
    float mean = block_reduce_sum(xv, red) * (1.f/DIMM);
    float d = xv - mean;
    float var = block_reduce_sum(d*d, red) * (1.f/DIMM);
    float inv = rsqrtf(var + 1e-5f);
    XN[(size_t)row*DIMM + j] = d*inv*ga[j] + ba[j];
}

// ---------------- combine split-K + bias + residual -> X, then LN -> XN ----------------
__global__ void combine_ln_kernel(const float* __restrict__ P, int ns,
                                  const float* __restrict__ bias, const float* __restrict__ R,
                                  const float* __restrict__ g, const float* __restrict__ bv,
                                  float* __restrict__ X, float* __restrict__ XN) {
    __shared__ float red[32];
    int row = blockIdx.x;
    int j = threadIdx.x;
    float v = bias[j] + R[(size_t)row*DIMM + j];
    for (int s = 0; s < ns; s++)
        v += P[(size_t)s*MROWS*DIMM + (size_t)row*DIMM + j];
    X[(size_t)row*DIMM + j] = v;
    float mean = block_reduce_sum(v, red) * (1.f/DIMM);
    float d = v - mean;
    float var = block_reduce_sum(d*d, red) * (1.f/DIMM);
    float inv = rsqrtf(var + 1e-5f);
    XN[(size_t)row*DIMM + j] = d*inv*g[j] + bv[j];
}

// ---------------- fp32 GEMM 128x64 tile, cp.async double buffer ----------------
// A staged row-major As[128][20]; W staged Ws[16][68]. Requires N%64==0, K%16==0.
__device__ __forceinline__ float gelu_exact(float v) {
    return 0.5f * v * (1.f + erff(v * 0.70710678118654752f));
}

template<int ACT>
__global__ void gemm_kernel(const float* __restrict__ A, const float* __restrict__ W,
                            const float* __restrict__ bias, const float* __restrict__ R,
                            float* __restrict__ C, int M, int K, int N) {
    __shared__ float As[2][128][20];
    __shared__ float Ws[2][16][68];
    int tid = threadIdx.x;
    int tx = tid & 15, ty = tid >> 4;          // ty: 16 row-groups of 8
    int m0 = blockIdx.y * 128, n0 = blockIdx.x * 64;
    float acc[8][4];
    #pragma unroll
    for (int i = 0; i < 8; i++)
        #pragma unroll
        for (int j = 0; j < 4; j++) acc[i][j] = 0.f;

    int am = tid >> 1, ak = (tid & 1) << 3;    // A: 128 rows, 2 thr/row, 8 floats each
    int wk = tid >> 4, wn4 = (tid & 15) << 2;  // W: 16 k x 64 n
    bool arow_ok = (m0 + am < M);
    int nslabs = K >> 4;

    uint32_t sa0a = smem_u32(&As[0][am][ak]);
    uint32_t sa0b = smem_u32(&As[0][am][ak + 4]);
    uint32_t sa1a = smem_u32(&As[1][am][ak]);
    uint32_t sa1b = smem_u32(&As[1][am][ak + 4]);
    uint32_t sw0 = smem_u32(&Ws[0][wk][wn4]);
    uint32_t sw1 = smem_u32(&Ws[1][wk][wn4]);

    cp16(sa0a, &A[(size_t)(m0 + am)*K + ak], arow_ok);
    cp16(sa0b, &A[(size_t)(m0 + am)*K + ak + 4], arow_ok);
    cp16(sw0, &W[(size_t)wk*N + n0 + wn4], true);
    cp_commit();

    for (int s = 0; s < nslabs; s++) {
        int cur = s & 1;
        if (s + 1 < nslabs) {
            int k0 = (s + 1) << 4;
            cp16(cur ? sa0a : sa1a, &A[(size_t)(m0 + am)*K + k0 + ak], arow_ok);
            cp16(cur ? sa0b : sa1b, &A[(size_t)(m0 + am)*K + k0 + ak + 4], arow_ok);
            cp16(cur ? sw0 : sw1, &W[(size_t)(k0 + wk)*N + n0 + wn4], true);
            cp_commit();
            cp_wait<1>();
        } else {
            cp_wait<0>();
        }
        __syncthreads();
        #pragma unroll
        for (int k = 0; k < 16; k++) {
            float a[8];
            #pragma unroll
            for (int i = 0; i < 8; i++) a[i] = As[cur][ty*8 + i][k];
            float w0 = Ws[cur][k][tx*4+0], w1 = Ws[cur][k][tx*4+1];
            float w2 = Ws[cur][k][tx*4+2], w3 = Ws[cur][k][tx*4+3];
            #pragma unroll
            for (int i = 0; i < 8; i++) {
                acc[i][0] += a[i]*w0; acc[i][1] += a[i]*w1;
                acc[i][2] += a[i]*w2; acc[i][3] += a[i]*w3;
            }
        }
        __syncthreads();
    }
    #pragma unroll
    for (int i = 0; i < 8; i++) {
        int m = m0 + ty*8 + i;
        if (m >= M) continue;
        #pragma unroll
        for (int j = 0; j < 4; j++) {
            int n = n0 + tx*4 + j;
            float v = acc[i][j] + bias[n];
            if (ACT == 1) v = gelu_exact(v);
            if (R != nullptr) v += R[(size_t)m*N + n];
            C[(size_t)m*N + n] = v;
        }
    }
}

// ---------------- split-K fp32 GEMM with cp.async: partial slabs (64x64) ----------------
__global__ void gemm_part_kernel(const float* __restrict__ A, const float* __restrict__ W,
                                 float* __restrict__ P, int M, int N, int klen) {
    __shared__ float As[2][64][20];
    __shared__ float Ws[2][16][68];
    int tid = threadIdx.x;
    int tx = tid & 15, ty = tid >> 4;
    int m0 = blockIdx.y * 64, n0 = blockIdx.x * 64;
    int kstart = blockIdx.z * klen;
    int Kfull = klen * gridDim.z;
    float* C = P + (size_t)blockIdx.z * M * N;
    float acc[4][4];
    #pragma unroll
    for (int i = 0; i < 4; i++)
        #pragma unroll
        for (int j = 0; j < 4; j++) acc[i][j] = 0.f;

    int am = tid >> 2, ak = (tid & 3) << 2;
    int wk = tid >> 4, wn4 = (tid & 15) << 2;
    bool arow_ok = (m0 + am < M);
    int nslabs = klen >> 4;

    uint32_t sa0 = smem_u32(&As[0][am][ak]);
    uint32_t sa1 = smem_u32(&As[1][am][ak]);
    uint32_t sw0 = smem_u32(&Ws[0][wk][wn4]);
    uint32_t sw1 = smem_u32(&Ws[1][wk][wn4]);

    cp16(sa0, &A[(size_t)(m0 + am)*Kfull + kstart + ak], arow_ok);
    cp16(sw0, &W[(size_t)(kstart + wk)*N + n0 + wn4], true);
    cp_commit();

    for (int s = 0; s < nslabs; s++) {
        int cur = s & 1;
        if (s + 1 < nslabs) {
            int k0 = kstart + ((s + 1) << 4);
            cp16(cur ? sa0 : sa1, &A[(size_t)(m0 + am)*Kfull + k0 + ak], arow_ok);
            cp16(cur ? sw0 : sw1, &W[(size_t)(k0 + wk)*N + n0 + wn4], true);
            cp_commit();
            cp_wait<1>();
        } else {
            cp_wait<0>();
        }
        __syncthreads();
        #pragma unroll
        for (int k = 0; k < 16; k++) {
            float a0 = As[cur][ty*4+0][k], a1 = As[cur][ty*4+1][k];
            float a2 = As[cur][ty*4+2][k], a3 = As[cur][ty*4+3][k];
            float w0 = Ws[cur][k][tx*4+0], w1 = Ws[cur][k][tx*4+1];
            float w2 = Ws[cur][k][tx*4+2], w3 = Ws[cur][k][tx*4+3];
            acc[0][0] += a0*w0; acc[0][1] += a0*w1; acc[0][2] += a0*w2; acc[0][3] += a0*w3;
            acc[1][0] += a1*w0; acc[1][1] += a1*w1; acc[1][2] += a1*w2; acc[1][3] += a1*w3;
            acc[2][0] += a2*w0; acc[2][1] += a2*w1; acc[2][2] += a2*w2; acc[2][3] += a2*w3;
            acc[3][0] += a3*w0; acc[3][1] += a3*w1; acc[3][2] += a3*w2; acc[3][3] += a3*w3;
        }
        __syncthreads();
    }
    #pragma unroll
    for (int i = 0; i < 4; i++) {
        int m = m0 + ty*4 + i;
        if (m >= M) continue;
        #pragma unroll
        for (int j = 0; j < 4; j++) {
            int n = n0 + tx*4 + j;
            C[(size_t)m*N + n] = acc[i][j];
        }
    }
}

// ---------------- tritt v7 tile: constant-trip q loop ----------------
template<int NJ>
__device__ __forceinline__ void tt_tile7(
    int tbase, uint32_t su, uint32_t sb, const float* cvec4,
    float rowacc[QB][4], float* colm4, int warp, int lane)
{
    const int g = lane >> 2, t4 = lane & 3;
    const int l2 = lane & 15, brow = l2 & 7, bkb = (l2 >> 3) << 4;
    const int arow = (lane & 7) + ((lane >> 3) & 1) * 8, akb = (lane >> 4) << 4;

    uint32_t bfr[4][NJ][2];
    #pragma unroll
    for (int ks = 0; ks < 4; ks++)
        #pragma unroll
        for (int j = 0; j < NJ; j++)
            ldm_x2(sb + swz((uint32_t)((tbase + j*8 + brow)*128 + ks*32 + bkb)), bfr[ks][j]);

    #pragma unroll
    for (int iq = 0; iq < QB; iq++) {
        const float* cv = cvec4 + iq*64;
        float acc[2][NJ][4];
        #pragma unroll
        for (int mc = 0; mc < 2; mc++)
            #pragma unroll
            for (int j = 0; j < NJ; j++)
                #pragma unroll
                for (int r = 0; r < 4; r++) acc[mc][j][r] = 0.f;

        #pragma unroll
        for (int ks = 0; ks < 4; ks++) {
            int k = ks*16 + 2*t4;
            __nv_bfloat162 p0 = __floats2bfloat162_rn(cv[k], cv[k+1]);
            __nv_bfloat162 p1 = __floats2bfloat162_rn(cv[k+8], cv[k+9]);
            uint32_t cs0 = *(uint32_t*)&p0, cs1 = *(uint32_t*)&p1;
            #pragma unroll
            for (int mc = 0; mc < 2; mc++) {
                uint32_t a[4];
                ldm_x4(su + swz((uint32_t)((warp*32 + mc*16 + arow)*128 + ks*32 + akb)), a);
                a[0] = hmul2u(a[0], cs0); a[1] = hmul2u(a[1], cs0);
                a[2] = hmul2u(a[2], cs1); a[3] = hmul2u(a[3], cs1);
                #pragma unroll
                for (int j = 0; j < NJ; j++) mma16816(acc[mc][j], a, bfr[ks][j]);
            }
        }

        // mask-free exp (pads are exp(0)=1; corrected in epilogue)
        #pragma unroll
        for (int mc = 0; mc < 2; mc++)
            #pragma unroll
            for (int j = 0; j < NJ; j++) {
                float e0 = __expf(acc[mc][j][0]), e1 = __expf(acc[mc][j][1]);
                float e2 = __expf(acc[mc][j][2]), e3 = __expf(acc[mc][j][3]);
                acc[mc][j][0] = e0; acc[mc][j][1] = e1;
                acc[mc][j][2] = e2; acc[mc][j][3] = e3;
                rowacc[iq][mc*2]   += e0 + e1;
                rowacc[iq][mc*2+1] += e2 + e3;
            }

        float* cq = colm4 + iq*BROWS;
        #pragma unroll
        for (int j = 0; j < NJ; j++) {
            float c0 = acc[0][j][0] + acc[0][j][2] + acc[1][j][0] + acc[1][j][2];
            float c1 = acc[0][j][1] + acc[0][j][3] + acc[1][j][1] + acc[1][j][3];
            #pragma unroll
            for (int o = 4; o <= 16; o <<= 1) {
                c0 += __shfl_xor_sync(0xffffffffu, c0, o);
                c1 += __shfl_xor_sync(0xffffffffu, c1, o);
            }
            if (g == 0) {
                int cc = tbase + j*8 + 2*t4;
                atomicAdd(&cq[cc], c0);
                atomicAdd(&cq[cc + 1], c1);
            }
        }
    }
}

// ---------------- trittention v7: one CTA per (b, h, q-block of 4) ----------------
__global__ __launch_bounds__(TT_THREADS, 2)
void tritt_mma_kernel(const float* __restrict__ abcde, float* __restrict__ Z) {
    extern __shared__ char smc[];
    float* redf  = (float*)(smc + SMB_RED);
    float* cvec4 = (float*)(smc + SMB_CVEC4);   // [4][64]
    float* rowm4 = (float*)(smc + SMB_ROWM4);   // [4][208]
    float* colm4 = (float*)(smc + SMB_COLM4);   // [4][208]
    uint32_t su = smem_u32(smc + SMB_A);
    uint32_t sb = smem_u32(smc + SMB_B);

    const int tid = threadIdx.x;
    const int warp = tid >> 5, lane = tid & 31;
    const int g = lane >> 2, t4 = lane & 3;

    int pair = blockIdx.x / NQCHUNK;
    int qc = blockIdx.x % NQCHUNK;
    int b = pair >> 2, h = pair & 3;
    const float* base = abcde + (size_t)b * TQ * FIVE;
    const int hoff = h * DH;
    int q0 = qc * QB;
    int nq = (TQ - q0 < QB) ? (TQ - q0) : QB;

    // ---- setup: A bf16 (224 rows, zero-padded), B bf16 (208 rows, zero-padded) ----
    for (int idx = tid; idx < MPAD*32; idx += TT_THREADS) {
        int s = idx >> 5, dp = (idx & 31) << 1;
        uint32_t val = 0u;
        if (s < TQ) {
            float2 av = *(const float2*)&base[(size_t)s*FIVE + hoff + dp];
            __nv_bfloat162 pp = __floats2bfloat162_rn(av.x, av.y);
            val = *(uint32_t*)&pp;
        }
        *(uint32_t*)(smc + SMB_A + swz((uint32_t)(s*128 + dp*2))) = val;
    }
    for (int idx = tid; idx < BROWS*32; idx += TT_THREADS) {
        int t = idx >> 5, dp = (idx & 31) << 1;
        uint32_t val = 0u;
        if (t < TQ) {
            float2 bv = *(const float2*)&base[(size_t)t*FIVE + DIMM + hoff + dp];
            __nv_bfloat162 pp = __floats2bfloat162_rn(bv.x, bv.y);
            val = *(uint32_t*)&pp;
        }
        *(uint32_t*)(smc + SMB_B + swz((uint32_t)(t*128 + dp*2))) = val;
    }
    {
        int qi = tid >> 6, d = tid & 63;
        cvec4[qi*64 + d] = (qi < nq)
            ? base[(size_t)(q0 + qi)*FIVE + 2*DIMM + hoff + d] * (1.0f/DH) : 0.f;
    }
    for (int i = tid; i < 4*BROWS; i += TT_THREADS) { rowm4[i] = 0.f; colm4[i] = 0.f; }
    __syncthreads();

    // ---- main loop: warps 0..6; tile-outer, constant-trip q-inner ----
    if (warp < 7) {
        float rowacc[QB][4];
        #pragma unroll
        for (int iq = 0; iq < QB; iq++)
            #pragma unroll
            for (int i = 0; i < 4; i++) rowacc[iq][i] = 0.f;

        tt_tile7<4>(  0, su, sb, cvec4, rowacc, colm4, warp, lane);
        tt_tile7<4>( 32, su, sb, cvec4, rowacc, colm4, warp, lane);
        tt_tile7<4>( 64, su, sb, cvec4, rowacc, colm4, warp, lane);
        tt_tile7<4>( 96, su, sb, cvec4, rowacc, colm4, warp, lane);
        tt_tile7<4>(128, su, sb, cvec4, rowacc, colm4, warp, lane);
        tt_tile7<4>(160, su, sb, cvec4, rowacc, colm4, warp, lane);
        tt_tile7<2>(192, su, sb, cvec4, rowacc, colm4, warp, lane);

        #pragma unroll
        for (int iq = 0; iq < QB; iq++) {
            #pragma unroll
            for (int i = 0; i < 4; i++) {
                rowacc[iq][i] += __shfl_xor_sync(0xffffffffu, rowacc[iq][i], 1);
                rowacc[iq][i] += __shfl_xor_sync(0xffffffffu, rowacc[iq][i], 2);
            }
            if (t4 == 0 && iq < nq) {
                float* rq = rowm4 + iq*BROWS;
                #pragma unroll
                for (int i = 0; i < 4; i++) {
                    int r = warp*32 + (i >> 1)*16 + (i & 1)*8 + g;
                    if (r < TQ) rq[r] = rowacc[iq][i];
                }
            }
        }
    }
    __syncthreads();

    // ---- Z total per q (raw; corrected by -ZCORR) ----
    int qi = tid >> 6, d = tid & 63;
    {
        const float* rq = rowm4 + qi*BROWS;
        float part = rq[d] + rq[d + 64] + rq[d + 128] + ((d < 16) ? rq[d + 192] : 0.f);
        #pragma unroll
        for (int o = 16; o > 0; o >>= 1) part += __shfl_xor_sync(0xffffffffu, part, o);
        if (lane == 0) redf[warp] = part;
    }
    __syncthreads();

    // ---- batched epilogue with pad corrections ----
    if (qi < nq) {
        float inv = 1.f / (redf[qi*2] + redf[qi*2 + 1] - ZCORR);
        const float* rq = rowm4 + qi*BROWS;
        const float* cq = colm4 + qi*BROWS;
        const float* Dp = base + 3*DIMM + hoff + d;
        const float* Ep = base + 4*DIMM + hoff + d;
        float accz = 0.f;
        #pragma unroll 4
        for (int s = 0; s < TQ; s++) {
            accz += (rq[s] - PADC) * Dp[(size_t)s*FIVE];
            accz += (cq[s] - PADR) * Ep[(size_t)s*FIVE];
        }
        Z[((size_t)(b*TQ + q0 + qi))*DIMM + hoff + d] = accz * inv;
    }
}

// ---------------- classifier head (in-block K split; XN already final-LN'd) ----------------
__global__ void head_kernel(const float* __restrict__ XN, const float* __restrict__ W,
                            const float* __restrict__ bias, float* __restrict__ out) {
    __shared__ float sacc[256];
    int tid = threadIdx.x;
    int c = tid & 63, kc = tid >> 6;
    int n = blockIdx.x * 64 + c;
    int b = blockIdx.y;
    const float* x = XN + (size_t)b * TQ * DIMM;
    float acc = 0.f;
    if (n < NCLS) {
        #pragma unroll 8
        for (int i = 0; i < 64; i++) {
            int k = kc*64 + i;
            acc += x[k] * W[(size_t)k*NCLS + n];
        }
    }
    sacc[tid] = acc;
    __syncthreads();
    if (kc == 0 && n < NCLS)
        out[(size_t)b*NCLS + n] = sacc[c] + sacc[64 + c] + sacc[128 + c] + sacc[192 + c] + bias[n];
}

// ---------------- host launch ----------------
extern "C" void kernel_launch(void* const* d_in, const int* in_sizes, int n_in,
                              void* d_out, int out_size) {
    const float* img         = (const float*)d_in[0];
    const float* patch_ln1_g = (const float*)d_in[1];
    const float* patch_ln1_b = (const float*)d_in[2];
    const float* patch_w     = (const float*)d_in[3];
    const float* patch_b     = (const float*)d_in[4];
    const float* patch_ln2_g = (const float*)d_in[5];
    const float* patch_ln2_b = (const float*)d_in[6];
    const float* pos_emb     = (const float*)d_in[7];
    const float* cls_token   = (const float*)d_in[8];
    const float* attn_ln_g   = (const float*)d_in[9];
    const float* attn_ln_b   = (const float*)d_in[10];
    const float* w_abcde     = (const float*)d_in[11];
    const float* b_abcde     = (const float*)d_in[12];
    const float* w_out       = (const float*)d_in[13];
    const float* b_out       = (const float*)d_in[14];
    const float* ff_ln_g     = (const float*)d_in[15];
    const float* ff_ln_b     = (const float*)d_in[16];
    const float* ff_w1       = (const float*)d_in[17];
    const float* ff_b1       = (const float*)d_in[18];
    const float* ff_w2       = (const float*)d_in[19];
    const float* ff_b2       = (const float*)d_in[20];
    const float* final_ln_g  = (const float*)d_in[21];
    const float* final_ln_b  = (const float*)d_in[22];
    const float* head_w      = (const float*)d_in[23];
    const float* head_b      = (const float*)d_in[24];
    float* out = (float*)d_out;

    float *pn, *x, *xn, *ab, *z, *hb, *pp;
    cudaGetSymbolAddress((void**)&pn, g_pn);
    cudaGetSymbolAddress((void**)&x,  g_x);
    cudaGetSymbolAddress((void**)&xn, g_xn);
    cudaGetSymbolAddress((void**)&ab, g_ab);
    cudaGetSymbolAddress((void**)&z,  g_z);
    cudaGetSymbolAddress((void**)&hb, g_h);
    cudaGetSymbolAddress((void**)&pp, g_part);

    cudaFuncSetAttribute(tritt_mma_kernel,
                         cudaFuncAttributeMaxDynamicSharedMemorySize, SMB_TOTAL);

    // patch embed: gather+LN1, split-K GEMM, fused combine+LN2+pos+attnLN0
    gather_ln_kernel<<<BATCH*NPATCH, 256>>>(img, patch_ln1_g, patch_ln1_b);
    gemm_part_kernel<<<dim3(4, 7, 3), 256>>>(pn, patch_w, pp, BATCH*NPATCH, DIMM, 256);
    assemble_fused_kernel<<<MROWS, 256>>>(pp, patch_b, patch_ln2_g, patch_ln2_b,
                                          cls_token, pos_emb, attn_ln_g, attn_ln_b, x, xn);

    // DIAGNOSTIC PROBE (launch #4 — captured by ncu): single-CTA tritt.
    // Reads g_ab (zero-init first call, replay-stable after); its z writes are
    // fully overwritten by the real tritt launches below, so output is unchanged.
    tritt_mma_kernel<<<1, TT_THREADS, SMB_TOTAL>>>(ab, z);

    for (int L = 0; L < 2; L++) {
        gemm_kernel<0><<<dim3(20, 4), 256>>>(xn, w_abcde + (size_t)L*DIMM*FIVE,
                                             b_abcde + L*FIVE, nullptr, ab,
                                             MROWS, DIMM, FIVE);
        tritt_mma_kernel<<<BATCH*HEADS*NQCHUNK, TT_THREADS, SMB_TOTAL>>>(ab, z);
        // out proj: split-K 4 (klen=64), combine fused with ff LN
        gemm_part_kernel<<<dim3(4, 7, 4), 256>>>(z, w_out + (size_t)L*DIMM*DIMM,
                                                 pp, MROWS, DIMM, 64);
        combine_ln_kernel<<<MROWS, 256>>>(pp, 4, b_out + L*DIMM, x,
                                          ff_ln_g + L*DIMM, ff_ln_b + L*DIMM, x, xn);
        gemm_kernel<1><<<dim3(16, 4), 256>>>(xn, ff_w1 + (size_t)L*DIMM*MLPD,
                                             ff_b1 + L*MLPD, nullptr, hb,
                                             MROWS, DIMM, MLPD);
        gemm_part_kernel<<<dim3(4, 7, 4), 256>>>(hb, ff_w2 + (size_t)L*MLPD*DIMM,
                                                 pp, MROWS, DIMM, 256);
        const float* ng = (L == 0) ? (attn_ln_g + DIMM) : final_ln_g;
        const float* nb = (L == 0) ? (attn_ln_b + DIMM) : final_ln_b;
        combine_ln_kernel<<<MROWS, 256>>>(pp, 4, ff_b2 + L*DIMM, x, ng, nb, x, xn);
    }

    head_kernel<<<dim3(16, BATCH), 256>>>(xn, head_w, head_b, out);
}

// round 14
// speedup vs baseline: 1.0259x; 1.0259x over previous
#include <cuda_runtime.h>
#include <cuda_bf16.h>
#include <cstdint>
#include <math.h>

// ---------------- problem constants ----------------
#define BATCH     2
#define TQ        197
#define DIMM      256
#define HEADS     4
#define DH        64
#define FIVE      1280
#define MLPD      1024
#define NCLS      1000
#define PATCH_DIM 768
#define NPATCH    196
#define MROWS     (BATCH*TQ)     // 394

// ---------------- tritt v8 constants ----------------
#define TT_THREADS 256
#define MPAD       224           // 7 warps x 32 rows
#define BROWS      208
#define QB         4
#define NQCHUNK    50            // ceil(197/4)
#define PADC       11.0f         // pad cols per valid row (208-197)
#define PADR       27.0f         // pad rows per valid col (224-197)
#define ZCORR      (197.0f*PADC) // 2167

// dynamic smem byte offsets (A/B 1024-aligned for swizzle)
#define SMB_RED    0                        // 32 floats (8 used)
#define SMB_CVEC4  256                      // 4*64 floats
#define SMB_ROWM4  1280                     // 4*208 floats
#define SMB_COLM4  4608                     // 4*208 floats
#define SMB_A      8192                     // 224 x 128B bf16 swizzled
#define SMB_B      (SMB_A + MPAD*128)       // 36864: 208 x 128B
#define SMB_TOTAL  (SMB_B + BROWS*128)      // 63488 bytes

__device__ __forceinline__ uint32_t swz(uint32_t off) {
    return off ^ ((off >> 3) & 0x70);
}

// ---------------- device scratch ----------------
__device__ float g_pn[BATCH*NPATCH*PATCH_DIM];
__device__ float g_x[MROWS*DIMM];
__device__ float g_xn[MROWS*DIMM];
__device__ float g_ab[MROWS*FIVE];
__device__ float g_z[MROWS*DIMM];
__device__ float g_h[MROWS*MLPD];
__device__ float g_part[4*MROWS*DIMM];   // split-K partials (max 4 slabs)

// ---------------- PTX helpers ----------------
__device__ __forceinline__ uint32_t smem_u32(const void* p) {
    uint32_t a;
    asm("{ .reg .u64 t; cvta.to.shared.u64 t, %1; cvt.u32.u64 %0, t; }" : "=r"(a) : "l"(p));
    return a;
}
__device__ __forceinline__ void ldm_x4(uint32_t addr, uint32_t* r) {
    asm volatile("ldmatrix.sync.aligned.m8n8.x4.shared.b16 {%0,%1,%2,%3}, [%4];"
                 : "=r"(r[0]), "=r"(r[1]), "=r"(r[2]), "=r"(r[3]) : "r"(addr));
}
__device__ __forceinline__ void ldm_x2(uint32_t addr, uint32_t* r) {
    asm volatile("ldmatrix.sync.aligned.m8n8.x2.shared.b16 {%0,%1}, [%2];"
                 : "=r"(r[0]), "=r"(r[1]) : "r"(addr));
}
__device__ __forceinline__ void mma16816(float* c, const uint32_t* a, const uint32_t* b) {
    asm volatile("mma.sync.aligned.m16n8k16.row.col.f32.bf16.bf16.f32 "
                 "{%0,%1,%2,%3}, {%4,%5,%6,%7}, {%8,%9}, {%0,%1,%2,%3};"
                 : "+f"(c[0]), "+f"(c[1]), "+f"(c[2]), "+f"(c[3])
                 : "r"(a[0]), "r"(a[1]), "r"(a[2]), "r"(a[3]), "r"(b[0]), "r"(b[1]));
}
__device__ __forceinline__ uint32_t hmul2u(uint32_t a, uint32_t b) {
    __nv_bfloat162 x = *(__nv_bfloat162*)&a, y = *(__nv_bfloat162*)&b;
    __nv_bfloat162 z = __hmul2(x, y);
    return *(uint32_t*)&z;
}
// cp.async helpers (sm_80+ portable)
__device__ __forceinline__ void cp16(uint32_t smem, const void* g, bool pred) {
    int sz = pred ? 16 : 0;
    asm volatile("cp.async.cg.shared.global [%0], [%1], 16, %2;"
                 :: "r"(smem), "l"(g), "r"(sz));
}
__device__ __forceinline__ void cp_commit() {
    asm volatile("cp.async.commit_group;" ::: "memory");
}
template<int N>
__device__ __forceinline__ void cp_wait() {
    asm volatile("cp.async.wait_group %0;" :: "n"(N) : "memory");
}

// ---------------- reductions (blockDim == 256, 8 warps) ----------------
__device__ __forceinline__ float block_reduce_sum(float v, float* red) {
    #pragma unroll
    for (int o = 16; o > 0; o >>= 1) v += __shfl_xor_sync(0xffffffffu, v, o);
    if ((threadIdx.x & 31) == 0) red[threadIdx.x >> 5] = v;
    __syncthreads();
    if (threadIdx.x < 32) {
        float r = (threadIdx.x < 8) ? red[threadIdx.x] : 0.f;
        #pragma unroll
        for (int o = 4; o > 0; o >>= 1) r += __shfl_xor_sync(0xffffffffu, r, o);
        if (threadIdx.x == 0) red[0] = r;
    }
    __syncthreads();
    float out = red[0];
    __syncthreads();
    return out;
}

// ---------------- fused patch gather + LN1 ----------------
__global__ void gather_ln_kernel(const float* __restrict__ img,
                                 const float* __restrict__ g, const float* __restrict__ bv) {
    __shared__ float red[32];
    int row = blockIdx.x;
    int b = row / NPATCH, pidx = row % NPATCH;
    int gh = pidx / 14, gw = pidx % 14;
    float v[3];
    #pragma unroll
    for (int r = 0; r < 3; r++) {
        int j = threadIdx.x + r*256;
        int p1 = j / 48, rem = j % 48, p2 = rem / 3, c = rem % 3;
        v[r] = img[(((size_t)b*3 + c)*224 + gh*16 + p1)*224 + gw*16 + p2];
    }
    float s = v[0] + v[1] + v[2];
    float mean = block_reduce_sum(s, red) * (1.f/PATCH_DIM);
    float vs = 0.f;
    #pragma unroll
    for (int r = 0; r < 3; r++) { float d = v[r]-mean; vs += d*d; }
    float var = block_reduce_sum(vs, red) * (1.f/PATCH_DIM);
    float inv = rsqrtf(var + 1e-5f);
    #pragma unroll
    for (int r = 0; r < 3; r++) {
        int j = threadIdx.x + r*256;
        g_pn[(size_t)row*PATCH_DIM + j] = (v[r]-mean)*inv*g[j] + bv[j];
    }
}

// ---------------- fused assemble: patch combine + LN2 + cls/pos + attn LN0 ----------------
__global__ void assemble_fused_kernel(const float* __restrict__ P,
                                      const float* __restrict__ pbias,
                                      const float* __restrict__ g2, const float* __restrict__ b2,
                                      const float* __restrict__ cls, const float* __restrict__ pos,
                                      const float* __restrict__ ga, const float* __restrict__ ba,
                                      float* __restrict__ X, float* __restrict__ XN) {
    __shared__ float red[32];
    int row = blockIdx.x;
    int b = row / TQ, t = row % TQ;
    int j = threadIdx.x;
    float xv;
    if (t == 0) {
        xv = cls[j] + pos[j];
    } else {
        int prow = b*NPATCH + t - 1;
        float v = pbias[j];
        #pragma unroll
        for (int s = 0; s < 3; s++)
            v += P[(size_t)s*BATCH*NPATCH*DIMM + (size_t)prow*DIMM + j];
        float mean = block_reduce_sum(v, red) * (1.f/DIMM);
        float d = v - mean;
        float var = block_reduce_sum(d*d, red) * (1.f/DIMM);
        float inv = rsqrtf(var + 1e-5f);
        xv = d*inv*g2[j] + b2[j] + pos[t*DIMM + j];
    }
    X[(size_t)row*DIMM + j] = xv;
    float mean = block_reduce_sum(xv, red) * (1.f/DIMM);
    float d = xv - mean;
    float var = block_reduce_sum(d*d, red) * (1.f/DIMM);
    float inv = rsqrtf(var + 1e-5f);
    XN[(size_t)row*DIMM + j] = d*inv*ga[j] + ba[j];
}

// ---------------- combine split-K + bias + residual -> X, then LN -> XN ----------------
__global__ void combine_ln_kernel(const float* __restrict__ P, int ns,
                                  const float* __restrict__ bias, const float* __restrict__ R,
                                  const float* __restrict__ g, const float* __restrict__ bv,
                                  float* __restrict__ X, float* __restrict__ XN) {
    __shared__ float red[32];
    int row = blockIdx.x;
    int j = threadIdx.x;
    float v = bias[j] + R[(size_t)row*DIMM + j];
    for (int s = 0; s < ns; s++)
        v += P[(size_t)s*MROWS*DIMM + (size_t)row*DIMM + j];
    X[(size_t)row*DIMM + j] = v;
    float mean = block_reduce_sum(v, red) * (1.f/DIMM);
    float d = v - mean;
    float var = block_reduce_sum(d*d, red) * (1.f/DIMM);
    float inv = rsqrtf(var + 1e-5f);
    XN[(size_t)row*DIMM + j] = d*inv*g[j] + bv[j];
}

// ---------------- fp32 GEMM 128x64 tile, cp.async double buffer ----------------
__device__ __forceinline__ float gelu_exact(float v) {
    return 0.5f * v * (1.f + erff(v * 0.70710678118654752f));
}

template<int ACT>
__global__ void gemm_kernel(const float* __restrict__ A, const float* __restrict__ W,
                            const float* __restrict__ bias, const float* __restrict__ R,
                            float* __restrict__ C, int M, int K, int N) {
    __shared__ float As[2][128][20];
    __shared__ float Ws[2][16][68];
    int tid = threadIdx.x;
    int tx = tid & 15, ty = tid >> 4;
    int m0 = blockIdx.y * 128, n0 = blockIdx.x * 64;
    float acc[8][4];
    #pragma unroll
    for (int i = 0; i < 8; i++)
        #pragma unroll
        for (int j = 0; j < 4; j++) acc[i][j] = 0.f;

    int am = tid >> 1, ak = (tid & 1) << 3;
    int wk = tid >> 4, wn4 = (tid & 15) << 2;
    bool arow_ok = (m0 + am < M);
    int nslabs = K >> 4;

    uint32_t sa0a = smem_u32(&As[0][am][ak]);
    uint32_t sa0b = smem_u32(&As[0][am][ak + 4]);
    uint32_t sa1a = smem_u32(&As[1][am][ak]);
    uint32_t sa1b = smem_u32(&As[1][am][ak + 4]);
    uint32_t sw0 = smem_u32(&Ws[0][wk][wn4]);
    uint32_t sw1 = smem_u32(&Ws[1][wk][wn4]);

    cp16(sa0a, &A[(size_t)(m0 + am)*K + ak], arow_ok);
    cp16(sa0b, &A[(size_t)(m0 + am)*K + ak + 4], arow_ok);
    cp16(sw0, &W[(size_t)wk*N + n0 + wn4], true);
    cp_commit();

    for (int s = 0; s < nslabs; s++) {
        int cur = s & 1;
        if (s + 1 < nslabs) {
            int k0 = (s + 1) << 4;
            cp16(cur ? sa0a : sa1a, &A[(size_t)(m0 + am)*K + k0 + ak], arow_ok);
            cp16(cur ? sa0b : sa1b, &A[(size_t)(m0 + am)*K + k0 + ak + 4], arow_ok);
            cp16(cur ? sw0 : sw1, &W[(size_t)(k0 + wk)*N + n0 + wn4], true);
            cp_commit();
            cp_wait<1>();
        } else {
            cp_wait<0>();
        }
        __syncthreads();
        #pragma unroll
        for (int k = 0; k < 16; k++) {
            float a[8];
            #pragma unroll
            for (int i = 0; i < 8; i++) a[i] = As[cur][ty*8 + i][k];
            float w0 = Ws[cur][k][tx*4+0], w1 = Ws[cur][k][tx*4+1];
            float w2 = Ws[cur][k][tx*4+2], w3 = Ws[cur][k][tx*4+3];
            #pragma unroll
            for (int i = 0; i < 8; i++) {
                acc[i][0] += a[i]*w0; acc[i][1] += a[i]*w1;
                acc[i][2] += a[i]*w2; acc[i][3] += a[i]*w3;
            }
        }
        __syncthreads();
    }
    #pragma unroll
    for (int i = 0; i < 8; i++) {
        int m = m0 + ty*8 + i;
        if (m >= M) continue;
        #pragma unroll
        for (int j = 0; j < 4; j++) {
            int n = n0 + tx*4 + j;
            float v = acc[i][j] + bias[n];
            if (ACT == 1) v = gelu_exact(v);
            if (R != nullptr) v += R[(size_t)m*N + n];
            C[(size_t)m*N + n] = v;
        }
    }
}

// ---------------- split-K fp32 GEMM with cp.async: partial slabs (64x64) ----------------
__global__ void gemm_part_kernel(const float* __restrict__ A, const float* __restrict__ W,
                                 float* __restrict__ P, int M, int N, int klen) {
    __shared__ float As[2][64][20];
    __shared__ float Ws[2][16][68];
    int tid = threadIdx.x;
    int tx = tid & 15, ty = tid >> 4;
    int m0 = blockIdx.y * 64, n0 = blockIdx.x * 64;
    int kstart = blockIdx.z * klen;
    int Kfull = klen * gridDim.z;
    float* C = P + (size_t)blockIdx.z * M * N;
    float acc[4][4];
    #pragma unroll
    for (int i = 0; i < 4; i++)
        #pragma unroll
        for (int j = 0; j < 4; j++) acc[i][j] = 0.f;

    int am = tid >> 2, ak = (tid & 3) << 2;
    int wk = tid >> 4, wn4 = (tid & 15) << 2;
    bool arow_ok = (m0 + am < M);
    int nslabs = klen >> 4;

    uint32_t sa0 = smem_u32(&As[0][am][ak]);
    uint32_t sa1 = smem_u32(&As[1][am][ak]);
    uint32_t sw0 = smem_u32(&Ws[0][wk][wn4]);
    uint32_t sw1 = smem_u32(&Ws[1][wk][wn4]);

    cp16(sa0, &A[(size_t)(m0 + am)*Kfull + kstart + ak], arow_ok);
    cp16(sw0, &W[(size_t)(kstart + wk)*N + n0 + wn4], true);
    cp_commit();

    for (int s = 0; s < nslabs; s++) {
        int cur = s & 1;
        if (s + 1 < nslabs) {
            int k0 = kstart + ((s + 1) << 4);
            cp16(cur ? sa0 : sa1, &A[(size_t)(m0 + am)*Kfull + k0 + ak], arow_ok);
            cp16(cur ? sw0 : sw1, &W[(size_t)(k0 + wk)*N + n0 + wn4], true);
            cp_commit();
            cp_wait<1>();
        } else {
            cp_wait<0>();
        }
        __syncthreads();
        #pragma unroll
        for (int k = 0; k < 16; k++) {
            float a0 = As[cur][ty*4+0][k], a1 = As[cur][ty*4+1][k];
            float a2 = As[cur][ty*4+2][k], a3 = As[cur][ty*4+3][k];
            float w0 = Ws[cur][k][tx*4+0], w1 = Ws[cur][k][tx*4+1];
            float w2 = Ws[cur][k][tx*4+2], w3 = Ws[cur][k][tx*4+3];
            acc[0][0] += a0*w0; acc[0][1] += a0*w1; acc[0][2] += a0*w2; acc[0][3] += a0*w3;
            acc[1][0] += a1*w0; acc[1][1] += a1*w1; acc[1][2] += a1*w2; acc[1][3] += a1*w3;
            acc[2][0] += a2*w0; acc[2][1] += a2*w1; acc[2][2] += a2*w2; acc[2][3] += a2*w3;
            acc[3][0] += a3*w0; acc[3][1] += a3*w1; acc[3][2] += a3*w2; acc[3][3] += a3*w3;
        }
        __syncthreads();
    }
    #pragma unroll
    for (int i = 0; i < 4; i++) {
        int m = m0 + ty*4 + i;
        if (m >= M) continue;
        #pragma unroll
        for (int j = 0; j < 4; j++) {
            int n = n0 + tx*4 + j;
            C[(size_t)m*N + n] = acc[i][j];
        }
    }
}

// ---------------- tritt v8 tile: single-q, low register pressure ----------------
template<int NJ>
__device__ __forceinline__ void tt_tile8(
    int tbase, uint32_t su, uint32_t sb, const uint32_t* cs,
    float* rowacc, float* cq, int warp, int lane)
{
    const int g = lane >> 2, t4 = lane & 3;
    const int l2 = lane & 15, brow = l2 & 7, bkb = (l2 >> 3) << 4;
    const int arow = (lane & 7) + ((lane >> 3) & 1) * 8, akb = (lane >> 4) << 4;

    float acc[2][NJ][4];
    #pragma unroll
    for (int mc = 0; mc < 2; mc++)
        #pragma unroll
        for (int j = 0; j < NJ; j++)
            #pragma unroll
            for (int r = 0; r < 4; r++) acc[mc][j][r] = 0.f;

    #pragma unroll
    for (int ks = 0; ks < 4; ks++) {
        uint32_t b[NJ][2];
        #pragma unroll
        for (int j = 0; j < NJ; j++)
            ldm_x2(sb + swz((uint32_t)((tbase + j*8 + brow)*128 + ks*32 + bkb)), b[j]);
        #pragma unroll
        for (int mc = 0; mc < 2; mc++) {
            uint32_t a[4];
            ldm_x4(su + swz((uint32_t)((warp*32 + mc*16 + arow)*128 + ks*32 + akb)), a);
            a[0] = hmul2u(a[0], cs[ks*2+0]); a[1] = hmul2u(a[1], cs[ks*2+0]);
            a[2] = hmul2u(a[2], cs[ks*2+1]); a[3] = hmul2u(a[3], cs[ks*2+1]);
            #pragma unroll
            for (int j = 0; j < NJ; j++) mma16816(acc[mc][j], a, b[j]);
        }
    }

    // mask-free exp (pads are exp(0)=1; corrected in epilogue)
    #pragma unroll
    for (int mc = 0; mc < 2; mc++)
        #pragma unroll
        for (int j = 0; j < NJ; j++) {
            float e0 = __expf(acc[mc][j][0]), e1 = __expf(acc[mc][j][1]);
            float e2 = __expf(acc[mc][j][2]), e3 = __expf(acc[mc][j][3]);
            acc[mc][j][0] = e0; acc[mc][j][1] = e1;
            acc[mc][j][2] = e2; acc[mc][j][3] = e3;
            rowacc[mc*2]   += e0 + e1;
            rowacc[mc*2+1] += e2 + e3;
        }

    // col sums: shfl reduce over g, atomics from lanes 0..3
    #pragma unroll
    for (int j = 0; j < NJ; j++) {
        float c0 = acc[0][j][0] + acc[0][j][2] + acc[1][j][0] + acc[1][j][2];
        float c1 = acc[0][j][1] + acc[0][j][3] + acc[1][j][1] + acc[1][j][3];
        #pragma unroll
        for (int o = 4; o <= 16; o <<= 1) {
            c0 += __shfl_xor_sync(0xffffffffu, c0, o);
            c1 += __shfl_xor_sync(0xffffffffu, c1, o);
        }
        if (g == 0) {
            int cc = tbase + j*8 + 2*t4;
            atomicAdd(&cq[cc], c0);
            atomicAdd(&cq[cc + 1], c1);
        }
    }
}

// ---------------- trittention v8: one CTA per (b, h, q-block of 4) ----------------
__global__ __launch_bounds__(TT_THREADS, 2)
void tritt_mma_kernel(const float* __restrict__ abcde, float* __restrict__ Z) {
    extern __shared__ char smc[];
    float* redf  = (float*)(smc + SMB_RED);
    float* cvec4 = (float*)(smc + SMB_CVEC4);   // [4][64]
    float* rowm4 = (float*)(smc + SMB_ROWM4);   // [4][208]
    float* colm4 = (float*)(smc + SMB_COLM4);   // [4][208]
    uint32_t su = smem_u32(smc + SMB_A);
    uint32_t sb = smem_u32(smc + SMB_B);

    const int tid = threadIdx.x;
    const int warp = tid >> 5, lane = tid & 31;
    const int g = lane >> 2, t4 = lane & 3;

    int pair = blockIdx.x / NQCHUNK;
    int qc = blockIdx.x % NQCHUNK;
    int b = pair >> 2, h = pair & 3;
    const float* base = abcde + (size_t)b * TQ * FIVE;
    const int hoff = h * DH;
    int q0 = qc * QB;
    int nq = (TQ - q0 < QB) ? (TQ - q0) : QB;

    // ---- setup: A bf16 (224 rows, zero-padded), B bf16 (208 rows, zero-padded) ----
    for (int idx = tid; idx < MPAD*32; idx += TT_THREADS) {
        int s = idx >> 5, dp = (idx & 31) << 1;
        uint32_t val = 0u;
        if (s < TQ) {
            float2 av = *(const float2*)&base[(size_t)s*FIVE + hoff + dp];
            __nv_bfloat162 pp = __floats2bfloat162_rn(av.x, av.y);
            val = *(uint32_t*)&pp;
        }
        *(uint32_t*)(smc + SMB_A + swz((uint32_t)(s*128 + dp*2))) = val;
    }
    for (int idx = tid; idx < BROWS*32; idx += TT_THREADS) {
        int t = idx >> 5, dp = (idx & 31) << 1;
        uint32_t val = 0u;
        if (t < TQ) {
            float2 bv = *(const float2*)&base[(size_t)t*FIVE + DIMM + hoff + dp];
            __nv_bfloat162 pp = __floats2bfloat162_rn(bv.x, bv.y);
            val = *(uint32_t*)&pp;
        }
        *(uint32_t*)(smc + SMB_B + swz((uint32_t)(t*128 + dp*2))) = val;
    }
    {
        int qi = tid >> 6, d = tid & 63;
        cvec4[qi*64 + d] = (qi < nq)
            ? base[(size_t)(q0 + qi)*FIVE + 2*DIMM + hoff + d] * (1.0f/DH) : 0.f;
    }
    for (int i = tid; i < 4*BROWS; i += TT_THREADS) { rowm4[i] = 0.f; colm4[i] = 0.f; }
    __syncthreads();

    // ---- main loop: warps 0..6; q-OUTER (not unrolled: keeps live set small) ----
    if (warp < 7) {
        #pragma unroll 1
        for (int iq = 0; iq < nq; iq++) {
            const float* cv = cvec4 + iq*64;
            uint32_t cs[8];
            #pragma unroll
            for (int ks = 0; ks < 4; ks++) {
                int k = ks*16 + 2*t4;
                __nv_bfloat162 p0 = __floats2bfloat162_rn(cv[k], cv[k+1]);
                __nv_bfloat162 p1 = __floats2bfloat162_rn(cv[k+8], cv[k+9]);
                cs[ks*2+0] = *(uint32_t*)&p0;
                cs[ks*2+1] = *(uint32_t*)&p1;
            }
            float rowacc[4] = {0.f, 0.f, 0.f, 0.f};
            float* cq = colm4 + iq*BROWS;

            tt_tile8<4>(  0, su, sb, cs, rowacc, cq, warp, lane);
            tt_tile8<4>( 32, su, sb, cs, rowacc, cq, warp, lane);
            tt_tile8<4>( 64, su, sb, cs, rowacc, cq, warp, lane);
            tt_tile8<4>( 96, su, sb, cs, rowacc, cq, warp, lane);
            tt_tile8<4>(128, su, sb, cs, rowacc, cq, warp, lane);
            tt_tile8<4>(160, su, sb, cs, rowacc, cq, warp, lane);
            tt_tile8<2>(192, su, sb, cs, rowacc, cq, warp, lane);

            #pragma unroll
            for (int i = 0; i < 4; i++) {
                rowacc[i] += __shfl_xor_sync(0xffffffffu, rowacc[i], 1);
                rowacc[i] += __shfl_xor_sync(0xffffffffu, rowacc[i], 2);
            }
            if (t4 == 0) {
                float* rq = rowm4 + iq*BROWS;
                #pragma unroll
                for (int i = 0; i < 4; i++) {
                    int r = warp*32 + (i >> 1)*16 + (i & 1)*8 + g;
                    if (r < TQ) rq[r] = rowacc[i];
                }
            }
        }
    }
    __syncthreads();

    // ---- Z total per q (raw; corrected by -ZCORR) ----
    int qi = tid >> 6, d = tid & 63;
    {
        const float* rq = rowm4 + qi*BROWS;
        float part = rq[d] + rq[d + 64] + rq[d + 128] + ((d < 16) ? rq[d + 192] : 0.f);
        #pragma unroll
        for (int o = 16; o > 0; o >>= 1) part += __shfl_xor_sync(0xffffffffu, part, o);
        if (lane == 0) redf[warp] = part;
    }
    __syncthreads();

    // ---- batched epilogue with pad corrections ----
    if (qi < nq) {
        float inv = 1.f / (redf[qi*2] + redf[qi*2 + 1] - ZCORR);
        const float* rq = rowm4 + qi*BROWS;
        const float* cq = colm4 + qi*BROWS;
        const float* Dp = base + 3*DIMM + hoff + d;
        const float* Ep = base + 4*DIMM + hoff + d;
        float accz = 0.f;
        #pragma unroll 4
        for (int s = 0; s < TQ; s++) {
            accz += (rq[s] - PADC) * Dp[(size_t)s*FIVE];
            accz += (cq[s] - PADR) * Ep[(size_t)s*FIVE];
        }
        Z[((size_t)(b*TQ + q0 + qi))*DIMM + hoff + d] = accz * inv;
    }
}

// ---------------- classifier head (in-block K split; XN already final-LN'd) ----------------
__global__ void head_kernel(const float* __restrict__ XN, const float* __restrict__ W,
                            const float* __restrict__ bias, float* __restrict__ out) {
    __shared__ float sacc[256];
    int tid = threadIdx.x;
    int c = tid & 63, kc = tid >> 6;
    int n = blockIdx.x * 64 + c;
    int b = blockIdx.y;
    const float* x = XN + (size_t)b * TQ * DIMM;
    float acc = 0.f;
    if (n < NCLS) {
        #pragma unroll 8
        for (int i = 0; i < 64; i++) {
            int k = kc*64 + i;
            acc += x[k] * W[(size_t)k*NCLS + n];
        }
    }
    sacc[tid] = acc;
    __syncthreads();
    if (kc == 0 && n < NCLS)
        out[(size_t)b*NCLS + n] = sacc[c] + sacc[64 + c] + sacc[128 + c] + sacc[192 + c] + bias[n];
}

// ---------------- host launch ----------------
extern "C" void kernel_launch(void* const* d_in, const int* in_sizes, int n_in,
                              void* d_out, int out_size) {
    const float* img         = (const float*)d_in[0];
    const float* patch_ln1_g = (const float*)d_in[1];
    const float* patch_ln1_b = (const float*)d_in[2];
    const float* patch_w     = (const float*)d_in[3];
    const float* patch_b     = (const float*)d_in[4];
    const float* patch_ln2_g = (const float*)d_in[5];
    const float* patch_ln2_b = (const float*)d_in[6];
    const float* pos_emb     = (const float*)d_in[7];
    const float* cls_token   = (const float*)d_in[8];
    const float* attn_ln_g   = (const float*)d_in[9];
    const float* attn_ln_b   = (const float*)d_in[10];
    const float* w_abcde     = (const float*)d_in[11];
    const float* b_abcde     = (const float*)d_in[12];
    const float* w_out       = (const float*)d_in[13];
    const float* b_out       = (const float*)d_in[14];
    const float* ff_ln_g     = (const float*)d_in[15];
    const float* ff_ln_b     = (const float*)d_in[16];
    const float* ff_w1       = (const float*)d_in[17];
    const float* ff_b1       = (const float*)d_in[18];
    const float* ff_w2       = (const float*)d_in[19];
    const float* ff_b2       = (const float*)d_in[20];
    const float* final_ln_g  = (const float*)d_in[21];
    const float* final_ln_b  = (const float*)d_in[22];
    const float* head_w      = (const float*)d_in[23];
    const float* head_b      = (const float*)d_in[24];
    float* out = (float*)d_out;

    float *pn, *x, *xn, *ab, *z, *hb, *pp;
    cudaGetSymbolAddress((void**)&pn, g_pn);
    cudaGetSymbolAddress((void**)&x,  g_x);
    cudaGetSymbolAddress((void**)&xn, g_xn);
    cudaGetSymbolAddress((void**)&ab, g_ab);
    cudaGetSymbolAddress((void**)&z,  g_z);
    cudaGetSymbolAddress((void**)&hb, g_h);
    cudaGetSymbolAddress((void**)&pp, g_part);

    cudaFuncSetAttribute(tritt_mma_kernel,
                         cudaFuncAttributeMaxDynamicSharedMemorySize, SMB_TOTAL);

    // patch embed: gather+LN1, split-K GEMM, fused combine+LN2+pos+attnLN0
    gather_ln_kernel<<<BATCH*NPATCH, 256>>>(img, patch_ln1_g, patch_ln1_b);
    gemm_part_kernel<<<dim3(4, 7, 3), 256>>>(pn, patch_w, pp, BATCH*NPATCH, DIMM, 256);
    assemble_fused_kernel<<<MROWS, 256>>>(pp, patch_b, patch_ln2_g, patch_ln2_b,
                                          cls_token, pos_emb, attn_ln_g, attn_ln_b, x, xn);

    // DIAGNOSTIC PROBE (launch #4 — captured by ncu): single-CTA tritt.
    // Reads g_ab (zero-init first call, replay-stable after); its z writes are
    // fully overwritten by the real tritt launches below, so output unchanged.
    tritt_mma_kernel<<<1, TT_THREADS, SMB_TOTAL>>>(ab, z);

    for (int L = 0; L < 2; L++) {
        gemm_kernel<0><<<dim3(20, 4), 256>>>(xn, w_abcde + (size_t)L*DIMM*FIVE,
                                             b_abcde + L*FIVE, nullptr, ab,
                                             MROWS, DIMM, FIVE);
        tritt_mma_kernel<<<BATCH*HEADS*NQCHUNK, TT_THREADS, SMB_TOTAL>>>(ab, z);
        // out proj: split-K 4 (klen=64), combine fused with ff LN
        gemm_part_kernel<<<dim3(4, 7, 4), 256>>>(z, w_out + (size_t)L*DIMM*DIMM,
                                                 pp, MROWS, DIMM, 64);
        combine_ln_kernel<<<MROWS, 256>>>(pp, 4, b_out + L*DIMM, x,
                                          ff_ln_g + L*DIMM, ff_ln_b + L*DIMM, x, xn);
        gemm_kernel<1><<<dim3(16, 4), 256>>>(xn, ff_w1 + (size_t)L*DIMM*MLPD,
                                             ff_b1 + L*MLPD, nullptr, hb,
                                             MROWS, DIMM, MLPD);
        gemm_part_kernel<<<dim3(4, 7, 4), 256>>>(hb, ff_w2 + (size_t)L*MLPD*DIMM,
                                                 pp, MROWS, DIMM, 256);
        const float* ng = (L == 0) ? (attn_ln_g + DIMM) : final_ln_g;
        const float* nb = (L == 0) ? (attn_ln_b + DIMM) : final_ln_b;
        combine_ln_kernel<<<MROWS, 256>>>(pp, 4, ff_b2 + L*DIMM, x, ng, nb, x, xn);
    }

    head_kernel<<<dim3(16, BATCH), 256>>>(xn, head_w, head_b, out);
}

// round 15
// speedup vs baseline: 1.3736x; 1.3389x over previous
#include <cuda_runtime.h>
#include <cuda_bf16.h>
#include <cstdint>
#include <math.h>

// ---------------- problem constants ----------------
#define BATCH     2
#define TQ        197
#define DIMM      256
#define HEADS     4
#define DH        64
#define FIVE      1280
#define MLPD      1024
#define NCLS      1000
#define PATCH_DIM 768
#define NPATCH    196
#define MROWS     (BATCH*TQ)     // 394

// ---------------- tritt v9 constants ----------------
#define TT_THREADS 256
#define MPAD       224           // 7 warps x 32 rows
#define BROWS      208
#define QB         4
#define NQCHUNK    50            // ceil(197/4)
#define PADC       11.0f         // pad cols per valid row (208-197)
#define PADR       27.0f         // pad rows per valid col (224-197)
#define ZCORR      (197.0f*PADC) // 2167

// dynamic smem byte offsets (A/B 1024-aligned for swizzle)
#define SMB_RED    0                        // 32 floats (8 used)
#define SMB_CVEC4  256                      // 4*64 floats
#define SMB_ROWM4  1280                     // 4*208 floats
#define SMB_COLM4  4608                     // 4*208 floats
#define SMB_A      8192                     // 224 x 128B bf16 swizzled
#define SMB_B      (SMB_A + MPAD*128)       // 36864: 208 x 128B
#define SMB_TOTAL  (SMB_B + BROWS*128)      // 63488 bytes

__device__ __forceinline__ uint32_t swz(uint32_t off) {
    return off ^ ((off >> 3) & 0x70);
}

// ---------------- device scratch ----------------
__device__ float g_pn[BATCH*NPATCH*PATCH_DIM];
__device__ float g_x[MROWS*DIMM];
__device__ float g_xn[MROWS*DIMM];
__device__ float g_ab[MROWS*FIVE];
__device__ float g_z[MROWS*DIMM];
__device__ float g_h[MROWS*MLPD];
__device__ float g_part[4*MROWS*DIMM];   // split-K partials (max 4 slabs)

// ---------------- PTX helpers ----------------
__device__ __forceinline__ uint32_t smem_u32(const void* p) {
    uint32_t a;
    asm("{ .reg .u64 t; cvta.to.shared.u64 t, %1; cvt.u32.u64 %0, t; }" : "=r"(a) : "l"(p));
    return a;
}
__device__ __forceinline__ void ldm_x4(uint32_t addr, uint32_t* r) {
    asm volatile("ldmatrix.sync.aligned.m8n8.x4.shared.b16 {%0,%1,%2,%3}, [%4];"
                 : "=r"(r[0]), "=r"(r[1]), "=r"(r[2]), "=r"(r[3]) : "r"(addr));
}
__device__ __forceinline__ void ldm_x2(uint32_t addr, uint32_t* r) {
    asm volatile("ldmatrix.sync.aligned.m8n8.x2.shared.b16 {%0,%1}, [%2];"
                 : "=r"(r[0]), "=r"(r[1]) : "r"(addr));
}
__device__ __forceinline__ void mma16816(float* c, const uint32_t* a, const uint32_t* b) {
    asm volatile("mma.sync.aligned.m16n8k16.row.col.f32.bf16.bf16.f32 "
                 "{%0,%1,%2,%3}, {%4,%5,%6,%7}, {%8,%9}, {%0,%1,%2,%3};"
                 : "+f"(c[0]), "+f"(c[1]), "+f"(c[2]), "+f"(c[3])
                 : "r"(a[0]), "r"(a[1]), "r"(a[2]), "r"(a[3]), "r"(b[0]), "r"(b[1]));
}
__device__ __forceinline__ uint32_t hmul2u(uint32_t a, uint32_t b) {
    __nv_bfloat162 x = *(__nv_bfloat162*)&a, y = *(__nv_bfloat162*)&b;
    __nv_bfloat162 z = __hmul2(x, y);
    return *(uint32_t*)&z;
}
// cp.async helpers (sm_80+ portable)
__device__ __forceinline__ void cp16(uint32_t smem, const void* g, bool pred) {
    int sz = pred ? 16 : 0;
    asm volatile("cp.async.cg.shared.global [%0], [%1], 16, %2;"
                 :: "r"(smem), "l"(g), "r"(sz));
}
__device__ __forceinline__ void cp_commit() {
    asm volatile("cp.async.commit_group;" ::: "memory");
}
template<int N>
__device__ __forceinline__ void cp_wait() {
    asm volatile("cp.async.wait_group %0;" :: "n"(N) : "memory");
}

// ---------------- reductions (blockDim == 256, 8 warps) ----------------
__device__ __forceinline__ float block_reduce_sum(float v, float* red) {
    #pragma unroll
    for (int o = 16; o > 0; o >>= 1) v += __shfl_xor_sync(0xffffffffu, v, o);
    if ((threadIdx.x & 31) == 0) red[threadIdx.x >> 5] = v;
    __syncthreads();
    if (threadIdx.x < 32) {
        float r = (threadIdx.x < 8) ? red[threadIdx.x] : 0.f;
        #pragma unroll
        for (int o = 4; o > 0; o >>= 1) r += __shfl_xor_sync(0xffffffffu, r, o);
        if (threadIdx.x == 0) red[0] = r;
    }
    __syncthreads();
    float out = red[0];
    __syncthreads();
    return out;
}

// ---------------- fused patch gather + LN1 ----------------
__global__ void gather_ln_kernel(const float* __restrict__ img,
                                 const float* __restrict__ g, const float* __restrict__ bv) {
    __shared__ float red[32];
    int row = blockIdx.x;
    int b = row / NPATCH, pidx = row % NPATCH;
    int gh = pidx / 14, gw = pidx % 14;
    float v[3];
    #pragma unroll
    for (int r = 0; r < 3; r++) {
        int j = threadIdx.x + r*256;
        int p1 = j / 48, rem = j % 48, p2 = rem / 3, c = rem % 3;
        v[r] = img[(((size_t)b*3 + c)*224 + gh*16 + p1)*224 + gw*16 + p2];
    }
    float s = v[0] + v[1] + v[2];
    float mean = block_reduce_sum(s, red) * (1.f/PATCH_DIM);
    float vs = 0.f;
    #pragma unroll
    for (int r = 0; r < 3; r++) { float d = v[r]-mean; vs += d*d; }
    float var = block_reduce_sum(vs, red) * (1.f/PATCH_DIM);
    float inv = rsqrtf(var + 1e-5f);
    #pragma unroll
    for (int r = 0; r < 3; r++) {
        int j = threadIdx.x + r*256;
        g_pn[(size_t)row*PATCH_DIM + j] = (v[r]-mean)*inv*g[j] + bv[j];
    }
}

// ---------------- fused assemble: patch combine + LN2 + cls/pos + attn LN0 ----------------
__global__ void assemble_fused_kernel(const float* __restrict__ P,
                                      const float* __restrict__ pbias,
                                      const float* __restrict__ g2, const float* __restrict__ b2,
                                      const float* __restrict__ cls, const float* __restrict__ pos,
                                      const float* __restrict__ ga, const float* __restrict__ ba,
                                      float* __restrict__ X, float* __restrict__ XN) {
    __shared__ float red[32];
    int row = blockIdx.x;
    int b = row / TQ, t = row % TQ;
    int j = threadIdx.x;
    float xv;
    if (t == 0) {
        xv = cls[j] + pos[j];
    } else {
        int prow = b*NPATCH + t - 1;
        float v = pbias[j];
        #pragma unroll
        for (int s = 0; s < 3; s++)
            v += P[(size_t)s*BATCH*NPATCH*DIMM + (size_t)prow*DIMM + j];
        float mean = block_reduce_sum(v, red) * (1.f/DIMM);
        float d = v - mean;
        float var = block_reduce_sum(d*d, red) * (1.f/DIMM);
        float inv = rsqrtf(var + 1e-5f);
        xv = d*inv*g2[j] + b2[j] + pos[t*DIMM + j];
    }
    X[(size_t)row*DIMM + j] = xv;
    float mean = block_reduce_sum(xv, red) * (1.f/DIMM);
    float d = xv - mean;
    float var = block_reduce_sum(d*d, red) * (1.f/DIMM);
    float inv = rsqrtf(var + 1e-5f);
    XN[(size_t)row*DIMM + j] = d*inv*ga[j] + ba[j];
}

// ---------------- combine split-K + bias + residual -> X, then LN -> XN ----------------
__global__ void combine_ln_kernel(const float* __restrict__ P, int ns,
                                  const float* __restrict__ bias, const float* __restrict__ R,
                                  const float* __restrict__ g, const float* __restrict__ bv,
                                  float* __restrict__ X, float* __restrict__ XN) {
    __shared__ float red[32];
    int row = blockIdx.x;
    int j = threadIdx.x;
    float v = bias[j] + R[(size_t)row*DIMM + j];
    for (int s = 0; s < ns; s++)
        v += P[(size_t)s*MROWS*DIMM + (size_t)row*DIMM + j];
    X[(size_t)row*DIMM + j] = v;
    float mean = block_reduce_sum(v, red) * (1.f/DIMM);
    float d = v - mean;
    float var = block_reduce_sum(d*d, red) * (1.f/DIMM);
    float inv = rsqrtf(var + 1e-5f);
    XN[(size_t)row*DIMM + j] = d*inv*g[j] + bv[j];
}

// ---------------- fp32 GEMM 128x64 tile, cp.async double buffer ----------------
__device__ __forceinline__ float gelu_exact(float v) {
    return 0.5f * v * (1.f + erff(v * 0.70710678118654752f));
}

template<int ACT>
__global__ void gemm_kernel(const float* __restrict__ A, const float* __restrict__ W,
                            const float* __restrict__ bias, const float* __restrict__ R,
                            float* __restrict__ C, int M, int K, int N) {
    __shared__ float As[2][128][20];
    __shared__ float Ws[2][16][68];
    int tid = threadIdx.x;
    int tx = tid & 15, ty = tid >> 4;
    int m0 = blockIdx.y * 128, n0 = blockIdx.x * 64;
    float acc[8][4];
    #pragma unroll
    for (int i = 0; i < 8; i++)
        #pragma unroll
        for (int j = 0; j < 4; j++) acc[i][j] = 0.f;

    int am = tid >> 1, ak = (tid & 1) << 3;
    int wk = tid >> 4, wn4 = (tid & 15) << 2;
    bool arow_ok = (m0 + am < M);
    int nslabs = K >> 4;

    uint32_t sa0a = smem_u32(&As[0][am][ak]);
    uint32_t sa0b = smem_u32(&As[0][am][ak + 4]);
    uint32_t sa1a = smem_u32(&As[1][am][ak]);
    uint32_t sa1b = smem_u32(&As[1][am][ak + 4]);
    uint32_t sw0 = smem_u32(&Ws[0][wk][wn4]);
    uint32_t sw1 = smem_u32(&Ws[1][wk][wn4]);

    cp16(sa0a, &A[(size_t)(m0 + am)*K + ak], arow_ok);
    cp16(sa0b, &A[(size_t)(m0 + am)*K + ak + 4], arow_ok);
    cp16(sw0, &W[(size_t)wk*N + n0 + wn4], true);
    cp_commit();

    for (int s = 0; s < nslabs; s++) {
        int cur = s & 1;
        if (s + 1 < nslabs) {
            int k0 = (s + 1) << 4;
            cp16(cur ? sa0a : sa1a, &A[(size_t)(m0 + am)*K + k0 + ak], arow_ok);
            cp16(cur ? sa0b : sa1b, &A[(size_t)(m0 + am)*K + k0 + ak + 4], arow_ok);
            cp16(cur ? sw0 : sw1, &W[(size_t)(k0 + wk)*N + n0 + wn4], true);
            cp_commit();
            cp_wait<1>();
        } else {
            cp_wait<0>();
        }
        __syncthreads();
        #pragma unroll
        for (int k = 0; k < 16; k++) {
            float a[8];
            #pragma unroll
            for (int i = 0; i < 8; i++) a[i] = As[cur][ty*8 + i][k];
            float w0 = Ws[cur][k][tx*4+0], w1 = Ws[cur][k][tx*4+1];
            float w2 = Ws[cur][k][tx*4+2], w3 = Ws[cur][k][tx*4+3];
            #pragma unroll
            for (int i = 0; i < 8; i++) {
                acc[i][0] += a[i]*w0; acc[i][1] += a[i]*w1;
                acc[i][2] += a[i]*w2; acc[i][3] += a[i]*w3;
            }
        }
        __syncthreads();
    }
    #pragma unroll
    for (int i = 0; i < 8; i++) {
        int m = m0 + ty*8 + i;
        if (m >= M) continue;
        #pragma unroll
        for (int j = 0; j < 4; j++) {
            int n = n0 + tx*4 + j;
            float v = acc[i][j] + bias[n];
            if (ACT == 1) v = gelu_exact(v);
            if (R != nullptr) v += R[(size_t)m*N + n];
            C[(size_t)m*N + n] = v;
        }
    }
}

// ---------------- split-K fp32 GEMM with cp.async: partial slabs (64x64) ----------------
__global__ void gemm_part_kernel(const float* __restrict__ A, const float* __restrict__ W,
                                 float* __restrict__ P, int M, int N, int klen) {
    __shared__ float As[2][64][20];
    __shared__ float Ws[2][16][68];
    int tid = threadIdx.x;
    int tx = tid & 15, ty = tid >> 4;
    int m0 = blockIdx.y * 64, n0 = blockIdx.x * 64;
    int kstart = blockIdx.z * klen;
    int Kfull = klen * gridDim.z;
    float* C = P + (size_t)blockIdx.z * M * N;
    float acc[4][4];
    #pragma unroll
    for (int i = 0; i < 4; i++)
        #pragma unroll
        for (int j = 0; j < 4; j++) acc[i][j] = 0.f;

    int am = tid >> 2, ak = (tid & 3) << 2;
    int wk = tid >> 4, wn4 = (tid & 15) << 2;
    bool arow_ok = (m0 + am < M);
    int nslabs = klen >> 4;

    uint32_t sa0 = smem_u32(&As[0][am][ak]);
    uint32_t sa1 = smem_u32(&As[1][am][ak]);
    uint32_t sw0 = smem_u32(&Ws[0][wk][wn4]);
    uint32_t sw1 = smem_u32(&Ws[1][wk][wn4]);

    cp16(sa0, &A[(size_t)(m0 + am)*Kfull + kstart + ak], arow_ok);
    cp16(sw0, &W[(size_t)(kstart + wk)*N + n0 + wn4], true);
    cp_commit();

    for (int s = 0; s < nslabs; s++) {
        int cur = s & 1;
        if (s + 1 < nslabs) {
            int k0 = kstart + ((s + 1) << 4);
            cp16(cur ? sa0 : sa1, &A[(size_t)(m0 + am)*Kfull + k0 + ak], arow_ok);
            cp16(cur ? sw0 : sw1, &W[(size_t)(k0 + wk)*N + n0 + wn4], true);
            cp_commit();
            cp_wait<1>();
        } else {
            cp_wait<0>();
        }
        __syncthreads();
        #pragma unroll
        for (int k = 0; k < 16; k++) {
            float a0 = As[cur][ty*4+0][k], a1 = As[cur][ty*4+1][k];
            float a2 = As[cur][ty*4+2][k], a3 = As[cur][ty*4+3][k];
            float w0 = Ws[cur][k][tx*4+0], w1 = Ws[cur][k][tx*4+1];
            float w2 = Ws[cur][k][tx*4+2], w3 = Ws[cur][k][tx*4+3];
            acc[0][0] += a0*w0; acc[0][1] += a0*w1; acc[0][2] += a0*w2; acc[0][3] += a0*w3;
            acc[1][0] += a1*w0; acc[1][1] += a1*w1; acc[1][2] += a1*w2; acc[1][3] += a1*w3;
            acc[2][0] += a2*w0; acc[2][1] += a2*w1; acc[2][2] += a2*w2; acc[2][3] += a2*w3;
            acc[3][0] += a3*w0; acc[3][1] += a3*w1; acc[3][2] += a3*w2; acc[3][3] += a3*w3;
        }
        __syncthreads();
    }
    #pragma unroll
    for (int i = 0; i < 4; i++) {
        int m = m0 + ty*4 + i;
        if (m >= M) continue;
        #pragma unroll
        for (int j = 0; j < 4; j++) {
            int n = n0 + tx*4 + j;
            C[(size_t)m*N + n] = acc[i][j];
        }
    }
}

// ---------------- tritt v9 tile: NJ=2 (16 cols), minimal live set ----------------
template<int NJ>
__device__ __forceinline__ void tt_tile9(
    int tbase, uint32_t su, uint32_t sb, const uint32_t* cs,
    float* rowacc, float* cq, int warp, int lane)
{
    const int g = lane >> 2, t4 = lane & 3;
    const int l2 = lane & 15, brow = l2 & 7, bkb = (l2 >> 3) << 4;
    const int arow = (lane & 7) + ((lane >> 3) & 1) * 8, akb = (lane >> 4) << 4;

    float acc[2][NJ][4];
    #pragma unroll
    for (int mc = 0; mc < 2; mc++)
        #pragma unroll
        for (int j = 0; j < NJ; j++)
            #pragma unroll
            for (int r = 0; r < 4; r++) acc[mc][j][r] = 0.f;

    #pragma unroll
    for (int ks = 0; ks < 4; ks++) {
        uint32_t b[NJ][2];
        #pragma unroll
        for (int j = 0; j < NJ; j++)
            ldm_x2(sb + swz((uint32_t)((tbase + j*8 + brow)*128 + ks*32 + bkb)), b[j]);
        #pragma unroll
        for (int mc = 0; mc < 2; mc++) {
            uint32_t a[4];
            ldm_x4(su + swz((uint32_t)((warp*32 + mc*16 + arow)*128 + ks*32 + akb)), a);
            a[0] = hmul2u(a[0], cs[ks*2+0]); a[1] = hmul2u(a[1], cs[ks*2+0]);
            a[2] = hmul2u(a[2], cs[ks*2+1]); a[3] = hmul2u(a[3], cs[ks*2+1]);
            #pragma unroll
            for (int j = 0; j < NJ; j++) mma16816(acc[mc][j], a, b[j]);
        }
    }

    // mask-free exp (pads are exp(0)=1; corrected in epilogue)
    #pragma unroll
    for (int mc = 0; mc < 2; mc++)
        #pragma unroll
        for (int j = 0; j < NJ; j++) {
            float e0 = __expf(acc[mc][j][0]), e1 = __expf(acc[mc][j][1]);
            float e2 = __expf(acc[mc][j][2]), e3 = __expf(acc[mc][j][3]);
            acc[mc][j][0] = e0; acc[mc][j][1] = e1;
            acc[mc][j][2] = e2; acc[mc][j][3] = e3;
            rowacc[mc*2]   += e0 + e1;
            rowacc[mc*2+1] += e2 + e3;
        }

    // col sums: shfl reduce over g, atomics from lanes 0..3
    #pragma unroll
    for (int j = 0; j < NJ; j++) {
        float c0 = acc[0][j][0] + acc[0][j][2] + acc[1][j][0] + acc[1][j][2];
        float c1 = acc[0][j][1] + acc[0][j][3] + acc[1][j][1] + acc[1][j][3];
        #pragma unroll
        for (int o = 4; o <= 16; o <<= 1) {
            c0 += __shfl_xor_sync(0xffffffffu, c0, o);
            c1 += __shfl_xor_sync(0xffffffffu, c1, o);
        }
        if (g == 0) {
            int cc = tbase + j*8 + 2*t4;
            atomicAdd(&cq[cc], c0);
            atomicAdd(&cq[cc + 1], c1);
        }
    }
}

// ---------------- trittention v9: 3 CTAs/SM (85-reg cap), NJ=2 tiles ----------------
__global__ __launch_bounds__(TT_THREADS, 3)
void tritt_mma_kernel(const float* __restrict__ abcde, float* __restrict__ Z) {
    extern __shared__ char smc[];
    float* redf  = (float*)(smc + SMB_RED);
    float* cvec4 = (float*)(smc + SMB_CVEC4);   // [4][64]
    float* rowm4 = (float*)(smc + SMB_ROWM4);   // [4][208]
    float* colm4 = (float*)(smc + SMB_COLM4);   // [4][208]
    uint32_t su = smem_u32(smc + SMB_A);
    uint32_t sb = smem_u32(smc + SMB_B);

    const int tid = threadIdx.x;
    const int warp = tid >> 5, lane = tid & 31;
    const int g = lane >> 2, t4 = lane & 3;

    int pair = blockIdx.x / NQCHUNK;
    int qc = blockIdx.x % NQCHUNK;
    int b = pair >> 2, h = pair & 3;
    const float* base = abcde + (size_t)b * TQ * FIVE;
    const int hoff = h * DH;
    int q0 = qc * QB;
    int nq = (TQ - q0 < QB) ? (TQ - q0) : QB;

    // ---- setup: A bf16 (224 rows, zero-padded), B bf16 (208 rows, zero-padded) ----
    for (int idx = tid; idx < MPAD*32; idx += TT_THREADS) {
        int s = idx >> 5, dp = (idx & 31) << 1;
        uint32_t val = 0u;
        if (s < TQ) {
            float2 av = *(const float2*)&base[(size_t)s*FIVE + hoff + dp];
            __nv_bfloat162 pp = __floats2bfloat162_rn(av.x, av.y);
            val = *(uint32_t*)&pp;
        }
        *(uint32_t*)(smc + SMB_A + swz((uint32_t)(s*128 + dp*2))) = val;
    }
    for (int idx = tid; idx < BROWS*32; idx += TT_THREADS) {
        int t = idx >> 5, dp = (idx & 31) << 1;
        uint32_t val = 0u;
        if (t < TQ) {
            float2 bv = *(const float2*)&base[(size_t)t*FIVE + DIMM + hoff + dp];
            __nv_bfloat162 pp = __floats2bfloat162_rn(bv.x, bv.y);
            val = *(uint32_t*)&pp;
        }
        *(uint32_t*)(smc + SMB_B + swz((uint32_t)(t*128 + dp*2))) = val;
    }
    {
        int qi = tid >> 6, d = tid & 63;
        cvec4[qi*64 + d] = (qi < nq)
            ? base[(size_t)(q0 + qi)*FIVE + 2*DIMM + hoff + d] * (1.0f/DH) : 0.f;
    }
    for (int i = tid; i < 4*BROWS; i += TT_THREADS) { rowm4[i] = 0.f; colm4[i] = 0.f; }
    __syncthreads();

    // ---- main loop: warps 0..6; q-OUTER (not unrolled), 13 NJ=2 tiles ----
    if (warp < 7) {
        #pragma unroll 1
        for (int iq = 0; iq < nq; iq++) {
            const float* cv = cvec4 + iq*64;
            uint32_t cs[8];
            #pragma unroll
            for (int ks = 0; ks < 4; ks++) {
                int k = ks*16 + 2*t4;
                __nv_bfloat162 p0 = __floats2bfloat162_rn(cv[k], cv[k+1]);
                __nv_bfloat162 p1 = __floats2bfloat162_rn(cv[k+8], cv[k+9]);
                cs[ks*2+0] = *(uint32_t*)&p0;
                cs[ks*2+1] = *(uint32_t*)&p1;
            }
            float rowacc[4] = {0.f, 0.f, 0.f, 0.f};
            float* cq = colm4 + iq*BROWS;

            #pragma unroll 1
            for (int tb = 0; tb < 208; tb += 16)
                tt_tile9<2>(tb, su, sb, cs, rowacc, cq, warp, lane);

            #pragma unroll
            for (int i = 0; i < 4; i++) {
                rowacc[i] += __shfl_xor_sync(0xffffffffu, rowacc[i], 1);
                rowacc[i] += __shfl_xor_sync(0xffffffffu, rowacc[i], 2);
            }
            if (t4 == 0) {
                float* rq = rowm4 + iq*BROWS;
                #pragma unroll
                for (int i = 0; i < 4; i++) {
                    int r = warp*32 + (i >> 1)*16 + (i & 1)*8 + g;
                    if (r < TQ) rq[r] = rowacc[i];
                }
            }
        }
    }
    __syncthreads();

    // ---- Z total per q (raw; corrected by -ZCORR) ----
    int qi = tid >> 6, d = tid & 63;
    {
        const float* rq = rowm4 + qi*BROWS;
        float part = rq[d] + rq[d + 64] + rq[d + 128] + ((d < 16) ? rq[d + 192] : 0.f);
        #pragma unroll
        for (int o = 16; o > 0; o >>= 1) part += __shfl_xor_sync(0xffffffffu, part, o);
        if (lane == 0) redf[warp] = part;
    }
    __syncthreads();

    // ---- batched epilogue with pad corrections ----
    if (qi < nq) {
        float inv = 1.f / (redf[qi*2] + redf[qi*2 + 1] - ZCORR);
        const float* rq = rowm4 + qi*BROWS;
        const float* cq = colm4 + qi*BROWS;
        const float* Dp = base + 3*DIMM + hoff + d;
        const float* Ep = base + 4*DIMM + hoff + d;
        float accz = 0.f;
        #pragma unroll 4
        for (int s = 0; s < TQ; s++) {
            accz += (rq[s] - PADC) * Dp[(size_t)s*FIVE];
            accz += (cq[s] - PADR) * Ep[(size_t)s*FIVE];
        }
        Z[((size_t)(b*TQ + q0 + qi))*DIMM + hoff + d] = accz * inv;
    }
}

// ---------------- classifier head (in-block K split; XN already final-LN'd) ----------------
__global__ void head_kernel(const float* __restrict__ XN, const float* __restrict__ W,
                            const float* __restrict__ bias, float* __restrict__ out) {
    __shared__ float sacc[256];
    int tid = threadIdx.x;
    int c = tid & 63, kc = tid >> 6;
    int n = blockIdx.x * 64 + c;
    int b = blockIdx.y;
    const float* x = XN + (size_t)b * TQ * DIMM;
    float acc = 0.f;
    if (n < NCLS) {
        #pragma unroll 8
        for (int i = 0; i < 64; i++) {
            int k = kc*64 + i;
            acc += x[k] * W[(size_t)k*NCLS + n];
        }
    }
    sacc[tid] = acc;
    __syncthreads();
    if (kc == 0 && n < NCLS)
        out[(size_t)b*NCLS + n] = sacc[c] + sacc[64 + c] + sacc[128 + c] + sacc[192 + c] + bias[n];
}

// ---------------- host launch ----------------
extern "C" void kernel_launch(void* const* d_in, const int* in_sizes, int n_in,
                              void* d_out, int out_size) {
    const float* img         = (const float*)d_in[0];
    const float* patch_ln1_g = (const float*)d_in[1];
    const float* patch_ln1_b = (const float*)d_in[2];
    const float* patch_w     = (const float*)d_in[3];
    const float* patch_b     = (const float*)d_in[4];
    const float* patch_ln2_g = (const float*)d_in[5];
    const float* patch_ln2_b = (const float*)d_in[6];
    const float* pos_emb     = (const float*)d_in[7];
    const float* cls_token   = (const float*)d_in[8];
    const float* attn_ln_g   = (const float*)d_in[9];
    const float* attn_ln_b   = (const float*)d_in[10];
    const float* w_abcde     = (const float*)d_in[11];
    const float* b_abcde     = (const float*)d_in[12];
    const float* w_out       = (const float*)d_in[13];
    const float* b_out       = (const float*)d_in[14];
    const float* ff_ln_g     = (const float*)d_in[15];
    const float* ff_ln_b     = (const float*)d_in[16];
    const float* ff_w1       = (const float*)d_in[17];
    const float* ff_b1       = (const float*)d_in[18];
    const float* ff_w2       = (const float*)d_in[19];
    const float* ff_b2       = (const float*)d_in[20];
    const float* final_ln_g  = (const float*)d_in[21];
    const float* final_ln_b  = (const float*)d_in[22];
    const float* head_w      = (const float*)d_in[23];
    const float* head_b      = (const float*)d_in[24];
    float* out = (float*)d_out;

    float *pn, *x, *xn, *ab, *z, *hb, *pp;
    cudaGetSymbolAddress((void**)&pn, g_pn);
    cudaGetSymbolAddress((void**)&x,  g_x);
    cudaGetSymbolAddress((void**)&xn, g_xn);
    cudaGetSymbolAddress((void**)&ab, g_ab);
    cudaGetSymbolAddress((void**)&z,  g_z);
    cudaGetSymbolAddress((void**)&hb, g_h);
    cudaGetSymbolAddress((void**)&pp, g_part);

    cudaFuncSetAttribute(tritt_mma_kernel,
                         cudaFuncAttributeMaxDynamicSharedMemorySize, SMB_TOTAL);

    // patch embed: gather+LN1, split-K GEMM, fused combine+LN2+pos+attnLN0
    gather_ln_kernel<<<BATCH*NPATCH, 256>>>(img, patch_ln1_g, patch_ln1_b);
    gemm_part_kernel<<<dim3(4, 7, 3), 256>>>(pn, patch_w, pp, BATCH*NPATCH, DIMM, 256);
    assemble_fused_kernel<<<MROWS, 256>>>(pp, patch_b, patch_ln2_g, patch_ln2_b,
                                          cls_token, pos_emb, attn_ln_g, attn_ln_b, x, xn);

    for (int L = 0; L < 2; L++) {
        gemm_kernel<0><<<dim3(20, 4), 256>>>(xn, w_abcde + (size_t)L*DIMM*FIVE,
                                             b_abcde + L*FIVE, nullptr, ab,
                                             MROWS, DIMM, FIVE);
        tritt_mma_kernel<<<BATCH*HEADS*NQCHUNK, TT_THREADS, SMB_TOTAL>>>(ab, z);
        // out proj: split-K 4 (klen=64), combine fused with ff LN
        gemm_part_kernel<<<dim3(4, 7, 4), 256>>>(z, w_out + (size_t)L*DIMM*DIMM,
                                                 pp, MROWS, DIMM, 64);
        combine_ln_kernel<<<MROWS, 256>>>(pp, 4, b_out + L*DIMM, x,
                                          ff_ln_g + L*DIMM, ff_ln_b + L*DIMM, x, xn);
        gemm_kernel<1><<<dim3(16, 4), 256>>>(xn, ff_w1 + (size_t)L*DIMM*MLPD,
                                             ff_b1 + L*MLPD, nullptr, hb,
                                             MROWS, DIMM, MLPD);
        gemm_part_kernel<<<dim3(4, 7, 4), 256>>>(hb, ff_w2 + (size_t)L*MLPD*DIMM,
                                                 pp, MROWS, DIMM, 256);
        const float* ng = (L == 0) ? (attn_ln_g + DIMM) : final_ln_g;
        const float* nb = (L == 0) ? (attn_ln_b + DIMM) : final_ln_b;
        combine_ln_kernel<<<MROWS, 256>>>(pp, 4, ff_b2 + L*DIMM, x, ng, nb, x, xn);
    }

    head_kernel<<<dim3(16, BATCH), 256>>>(xn, head_w, head_b, out);
}

// round 16
// speedup vs baseline: 1.5421x; 1.1227x over previous
#include <cuda_runtime.h>
#include <cuda_bf16.h>
#include <cstdint>
#include <math.h>

// ---------------- problem constants ----------------
#define BATCH     2
#define TQ        197
#define DIMM      256
#define HEADS     4
#define DH        64
#define FIVE      1280
#define MLPD      1024
#define NCLS      1000
#define PATCH_DIM 768
#define NPATCH    196
#define MROWS     (BATCH*TQ)     // 394

// ---------------- tritt v9 constants ----------------
#define TT_THREADS 256
#define MPAD       224           // 7 warps x 32 rows
#define BROWS      208
#define QB         4
#define NQCHUNK    50            // ceil(197/4)
#define PADC       11.0f         // pad cols per valid row (208-197)
#define PADR       27.0f         // pad rows per valid col (224-197)
#define ZCORR      (197.0f*PADC) // 2167

// dynamic smem byte offsets (A/B 1024-aligned for swizzle)
#define SMB_RED    0                        // 32 floats (8 used)
#define SMB_CVEC4  256                      // 4*64 floats
#define SMB_ROWM4  1280                     // 4*208 floats
#define SMB_COLM4  4608                     // 4*208 floats
#define SMB_A      8192                     // 224 x 128B bf16 swizzled
#define SMB_B      (SMB_A + MPAD*128)       // 36864: 208 x 128B
#define SMB_TOTAL  (SMB_B + BROWS*128)      // 63488 bytes

__device__ __forceinline__ uint32_t swz(uint32_t off) {
    return off ^ ((off >> 3) & 0x70);
}

// ---------------- device scratch ----------------
__device__ float g_pn[BATCH*NPATCH*PATCH_DIM];
__device__ float g_x[MROWS*DIMM];
__device__ float g_xn[MROWS*DIMM];
__device__ float g_ab[MROWS*FIVE];
__device__ float g_z[MROWS*DIMM];
__device__ float g_h[MROWS*MLPD];
__device__ float g_part[4*MROWS*DIMM];   // split-K partials (max 4 slabs)

// ---------------- PTX helpers ----------------
__device__ __forceinline__ uint32_t smem_u32(const void* p) {
    uint32_t a;
    asm("{ .reg .u64 t; cvta.to.shared.u64 t, %1; cvt.u32.u64 %0, t; }" : "=r"(a) : "l"(p));
    return a;
}
__device__ __forceinline__ void ldm_x4(uint32_t addr, uint32_t* r) {
    asm volatile("ldmatrix.sync.aligned.m8n8.x4.shared.b16 {%0,%1,%2,%3}, [%4];"
                 : "=r"(r[0]), "=r"(r[1]), "=r"(r[2]), "=r"(r[3]) : "r"(addr));
}
__device__ __forceinline__ void ldm_x2(uint32_t addr, uint32_t* r) {
    asm volatile("ldmatrix.sync.aligned.m8n8.x2.shared.b16 {%0,%1}, [%2];"
                 : "=r"(r[0]), "=r"(r[1]) : "r"(addr));
}
__device__ __forceinline__ void mma16816(float* c, const uint32_t* a, const uint32_t* b) {
    asm volatile("mma.sync.aligned.m16n8k16.row.col.f32.bf16.bf16.f32 "
                 "{%0,%1,%2,%3}, {%4,%5,%6,%7}, {%8,%9}, {%0,%1,%2,%3};"
                 : "+f"(c[0]), "+f"(c[1]), "+f"(c[2]), "+f"(c[3])
                 : "r"(a[0]), "r"(a[1]), "r"(a[2]), "r"(a[3]), "r"(b[0]), "r"(b[1]));
}
__device__ __forceinline__ uint32_t hmul2u(uint32_t a, uint32_t b) {
    __nv_bfloat162 x = *(__nv_bfloat162*)&a, y = *(__nv_bfloat162*)&b;
    __nv_bfloat162 z = __hmul2(x, y);
    return *(uint32_t*)&z;
}
// cp.async helpers (sm_80+ portable)
__device__ __forceinline__ void cp16(uint32_t smem, const void* g, bool pred) {
    int sz = pred ? 16 : 0;
    asm volatile("cp.async.cg.shared.global [%0], [%1], 16, %2;"
                 :: "r"(smem), "l"(g), "r"(sz));
}
__device__ __forceinline__ void cp_commit() {
    asm volatile("cp.async.commit_group;" ::: "memory");
}
template<int N>
__device__ __forceinline__ void cp_wait() {
    asm volatile("cp.async.wait_group %0;" :: "n"(N) : "memory");
}

// ---------------- reductions (blockDim == 256, 8 warps) ----------------
__device__ __forceinline__ float block_reduce_sum(float v, float* red) {
    #pragma unroll
    for (int o = 16; o > 0; o >>= 1) v += __shfl_xor_sync(0xffffffffu, v, o);
    if ((threadIdx.x & 31) == 0) red[threadIdx.x >> 5] = v;
    __syncthreads();
    if (threadIdx.x < 32) {
        float r = (threadIdx.x < 8) ? red[threadIdx.x] : 0.f;
        #pragma unroll
        for (int o = 4; o > 0; o >>= 1) r += __shfl_xor_sync(0xffffffffu, r, o);
        if (threadIdx.x == 0) red[0] = r;
    }
    __syncthreads();
    float out = red[0];
    __syncthreads();
    return out;
}

// ---------------- fused patch gather + LN1 ----------------
__global__ void gather_ln_kernel(const float* __restrict__ img,
                                 const float* __restrict__ g, const float* __restrict__ bv) {
    __shared__ float red[32];
    int row = blockIdx.x;
    int b = row / NPATCH, pidx = row % NPATCH;
    int gh = pidx / 14, gw = pidx % 14;
    float v[3];
    #pragma unroll
    for (int r = 0; r < 3; r++) {
        int j = threadIdx.x + r*256;
        int p1 = j / 48, rem = j % 48, p2 = rem / 3, c = rem % 3;
        v[r] = img[(((size_t)b*3 + c)*224 + gh*16 + p1)*224 + gw*16 + p2];
    }
    float s = v[0] + v[1] + v[2];
    float mean = block_reduce_sum(s, red) * (1.f/PATCH_DIM);
    float vs = 0.f;
    #pragma unroll
    for (int r = 0; r < 3; r++) { float d = v[r]-mean; vs += d*d; }
    float var = block_reduce_sum(vs, red) * (1.f/PATCH_DIM);
    float inv = rsqrtf(var + 1e-5f);
    #pragma unroll
    for (int r = 0; r < 3; r++) {
        int j = threadIdx.x + r*256;
        g_pn[(size_t)row*PATCH_DIM + j] = (v[r]-mean)*inv*g[j] + bv[j];
    }
}

// ---------------- fused assemble: patch combine + LN2 + cls/pos + attn LN0 ----------------
__global__ void assemble_fused_kernel(const float* __restrict__ P,
                                      const float* __restrict__ pbias,
                                      const float* __restrict__ g2, const float* __restrict__ b2,
                                      const float* __restrict__ cls, const float* __restrict__ pos,
                                      const float* __restrict__ ga, const float* __restrict__ ba,
                                      float* __restrict__ X, float* __restrict__ XN) {
    __shared__ float red[32];
    int row = blockIdx.x;
    int b = row / TQ, t = row % TQ;
    int j = threadIdx.x;
    float xv;
    if (t == 0) {
        xv = cls[j] + pos[j];
    } else {
        int prow = b*NPATCH + t - 1;
        float v = pbias[j];
        #pragma unroll
        for (int s = 0; s < 3; s++)
            v += P[(size_t)s*BATCH*NPATCH*DIMM + (size_t)prow*DIMM + j];
        float mean = block_reduce_sum(v, red) * (1.f/DIMM);
        float d = v - mean;
        float var = block_reduce_sum(d*d, red) * (1.f/DIMM);
        float inv = rsqrtf(var + 1e-5f);
        xv = d*inv*g2[j] + b2[j] + pos[t*DIMM + j];
    }
    X[(size_t)row*DIMM + j] = xv;
    float mean = block_reduce_sum(xv, red) * (1.f/DIMM);
    float d = xv - mean;
    float var = block_reduce_sum(d*d, red) * (1.f/DIMM);
    float inv = rsqrtf(var + 1e-5f);
    XN[(size_t)row*DIMM + j] = d*inv*ga[j] + ba[j];
}

// ---------------- combine split-K + bias + residual -> X, then LN -> XN ----------------
__global__ void combine_ln_kernel(const float* __restrict__ P, int ns,
                                  const float* __restrict__ bias, const float* __restrict__ R,
                                  const float* __restrict__ g, const float* __restrict__ bv,
                                  float* __restrict__ X, float* __restrict__ XN) {
    __shared__ float red[32];
    int row = blockIdx.x;
    int j = threadIdx.x;
    float v = bias[j] + R[(size_t)row*DIMM + j];
    for (int s = 0; s < ns; s++)
        v += P[(size_t)s*MROWS*DIMM + (size_t)row*DIMM + j];
    X[(size_t)row*DIMM + j] = v;
    float mean = block_reduce_sum(v, red) * (1.f/DIMM);
    float d = v - mean;
    float var = block_reduce_sum(d*d, red) * (1.f/DIMM);
    float inv = rsqrtf(var + 1e-5f);
    XN[(size_t)row*DIMM + j] = d*inv*g[j] + bv[j];
}

// ---------------- fp32 GEMM 64x64 tile, cp.async double buffer (R12 known-good) ----------------
__device__ __forceinline__ float gelu_exact(float v) {
    return 0.5f * v * (1.f + erff(v * 0.70710678118654752f));
}

template<int ACT>
__global__ void gemm_kernel(const float* __restrict__ A, const float* __restrict__ W,
                            const float* __restrict__ bias, const float* __restrict__ R,
                            float* __restrict__ C, int M, int K, int N) {
    __shared__ float As[2][64][20];
    __shared__ float Ws[2][16][68];
    int tid = threadIdx.x;
    int tx = tid & 15, ty = tid >> 4;
    int m0 = blockIdx.y * 64, n0 = blockIdx.x * 64;
    float acc[4][4];
    #pragma unroll
    for (int i = 0; i < 4; i++)
        #pragma unroll
        for (int j = 0; j < 4; j++) acc[i][j] = 0.f;

    int am = tid >> 2, ak = (tid & 3) << 2;
    int wk = tid >> 4, wn4 = (tid & 15) << 2;
    bool arow_ok = (m0 + am < M);
    int nslabs = K >> 4;

    uint32_t sa0 = smem_u32(&As[0][am][ak]);
    uint32_t sa1 = smem_u32(&As[1][am][ak]);
    uint32_t sw0 = smem_u32(&Ws[0][wk][wn4]);
    uint32_t sw1 = smem_u32(&Ws[1][wk][wn4]);

    cp16(sa0, &A[(size_t)(m0 + am)*K + ak], arow_ok);
    cp16(sw0, &W[(size_t)wk*N + n0 + wn4], true);
    cp_commit();

    for (int s = 0; s < nslabs; s++) {
        int cur = s & 1;
        if (s + 1 < nslabs) {
            int k0 = (s + 1) << 4;
            cp16(cur ? sa0 : sa1, &A[(size_t)(m0 + am)*K + k0 + ak], arow_ok);
            cp16(cur ? sw0 : sw1, &W[(size_t)(k0 + wk)*N + n0 + wn4], true);
            cp_commit();
            cp_wait<1>();
        } else {
            cp_wait<0>();
        }
        __syncthreads();
        #pragma unroll
        for (int k = 0; k < 16; k++) {
            float a0 = As[cur][ty*4+0][k], a1 = As[cur][ty*4+1][k];
            float a2 = As[cur][ty*4+2][k], a3 = As[cur][ty*4+3][k];
            float w0 = Ws[cur][k][tx*4+0], w1 = Ws[cur][k][tx*4+1];
            float w2 = Ws[cur][k][tx*4+2], w3 = Ws[cur][k][tx*4+3];
            acc[0][0] += a0*w0; acc[0][1] += a0*w1; acc[0][2] += a0*w2; acc[0][3] += a0*w3;
            acc[1][0] += a1*w0; acc[1][1] += a1*w1; acc[1][2] += a1*w2; acc[1][3] += a1*w3;
            acc[2][0] += a2*w0; acc[2][1] += a2*w1; acc[2][2] += a2*w2; acc[2][3] += a2*w3;
            acc[3][0] += a3*w0; acc[3][1] += a3*w1; acc[3][2] += a3*w2; acc[3][3] += a3*w3;
        }
        __syncthreads();
    }
    #pragma unroll
    for (int i = 0; i < 4; i++) {
        int m = m0 + ty*4 + i;
        if (m >= M) continue;
        #pragma unroll
        for (int j = 0; j < 4; j++) {
            int n = n0 + tx*4 + j;
            float v = acc[i][j] + bias[n];
            if (ACT == 1) v = gelu_exact(v);
            if (R != nullptr) v += R[(size_t)m*N + n];
            C[(size_t)m*N + n] = v;
        }
    }
}

// ---------------- split-K fp32 GEMM with cp.async: partial slabs (64x64) ----------------
__global__ void gemm_part_kernel(const float* __restrict__ A, const float* __restrict__ W,
                                 float* __restrict__ P, int M, int N, int klen) {
    __shared__ float As[2][64][20];
    __shared__ float Ws[2][16][68];
    int tid = threadIdx.x;
    int tx = tid & 15, ty = tid >> 4;
    int m0 = blockIdx.y * 64, n0 = blockIdx.x * 64;
    int kstart = blockIdx.z * klen;
    int Kfull = klen * gridDim.z;
    float* C = P + (size_t)blockIdx.z * M * N;
    float acc[4][4];
    #pragma unroll
    for (int i = 0; i < 4; i++)
        #pragma unroll
        for (int j = 0; j < 4; j++) acc[i][j] = 0.f;

    int am = tid >> 2, ak = (tid & 3) << 2;
    int wk = tid >> 4, wn4 = (tid & 15) << 2;
    bool arow_ok = (m0 + am < M);
    int nslabs = klen >> 4;

    uint32_t sa0 = smem_u32(&As[0][am][ak]);
    uint32_t sa1 = smem_u32(&As[1][am][ak]);
    uint32_t sw0 = smem_u32(&Ws[0][wk][wn4]);
    uint32_t sw1 = smem_u32(&Ws[1][wk][wn4]);

    cp16(sa0, &A[(size_t)(m0 + am)*Kfull + kstart + ak], arow_ok);
    cp16(sw0, &W[(size_t)(kstart + wk)*N + n0 + wn4], true);
    cp_commit();

    for (int s = 0; s < nslabs; s++) {
        int cur = s & 1;
        if (s + 1 < nslabs) {
            int k0 = kstart + ((s + 1) << 4);
            cp16(cur ? sa0 : sa1, &A[(size_t)(m0 + am)*Kfull + k0 + ak], arow_ok);
            cp16(cur ? sw0 : sw1, &W[(size_t)(k0 + wk)*N + n0 + wn4], true);
            cp_commit();
            cp_wait<1>();
        } else {
            cp_wait<0>();
        }
        __syncthreads();
        #pragma unroll
        for (int k = 0; k < 16; k++) {
            float a0 = As[cur][ty*4+0][k], a1 = As[cur][ty*4+1][k];
            float a2 = As[cur][ty*4+2][k], a3 = As[cur][ty*4+3][k];
            float w0 = Ws[cur][k][tx*4+0], w1 = Ws[cur][k][tx*4+1];
            float w2 = Ws[cur][k][tx*4+2], w3 = Ws[cur][k][tx*4+3];
            acc[0][0] += a0*w0; acc[0][1] += a0*w1; acc[0][2] += a0*w2; acc[0][3] += a0*w3;
            acc[1][0] += a1*w0; acc[1][1] += a1*w1; acc[1][2] += a1*w2; acc[1][3] += a1*w3;
            acc[2][0] += a2*w0; acc[2][1] += a2*w1; acc[2][2] += a2*w2; acc[2][3] += a2*w3;
            acc[3][0] += a3*w0; acc[3][1] += a3*w1; acc[3][2] += a3*w2; acc[3][3] += a3*w3;
        }
        __syncthreads();
    }
    #pragma unroll
    for (int i = 0; i < 4; i++) {
        int m = m0 + ty*4 + i;
        if (m >= M) continue;
        #pragma unroll
        for (int j = 0; j < 4; j++) {
            int n = n0 + tx*4 + j;
            C[(size_t)m*N + n] = acc[i][j];
        }
    }
}

// ---------------- tritt v9 tile: NJ=2 (16 cols), minimal live set ----------------
template<int NJ>
__device__ __forceinline__ void tt_tile9(
    int tbase, uint32_t su, uint32_t sb, const uint32_t* cs,
    float* rowacc, float* cq, int warp, int lane)
{
    const int g = lane >> 2, t4 = lane & 3;
    const int l2 = lane & 15, brow = l2 & 7, bkb = (l2 >> 3) << 4;
    const int arow = (lane & 7) + ((lane >> 3) & 1) * 8, akb = (lane >> 4) << 4;

    float acc[2][NJ][4];
    #pragma unroll
    for (int mc = 0; mc < 2; mc++)
        #pragma unroll
        for (int j = 0; j < NJ; j++)
            #pragma unroll
            for (int r = 0; r < 4; r++) acc[mc][j][r] = 0.f;

    #pragma unroll
    for (int ks = 0; ks < 4; ks++) {
        uint32_t b[NJ][2];
        #pragma unroll
        for (int j = 0; j < NJ; j++)
            ldm_x2(sb + swz((uint32_t)((tbase + j*8 + brow)*128 + ks*32 + bkb)), b[j]);
        #pragma unroll
        for (int mc = 0; mc < 2; mc++) {
            uint32_t a[4];
            ldm_x4(su + swz((uint32_t)((warp*32 + mc*16 + arow)*128 + ks*32 + akb)), a);
            a[0] = hmul2u(a[0], cs[ks*2+0]); a[1] = hmul2u(a[1], cs[ks*2+0]);
            a[2] = hmul2u(a[2], cs[ks*2+1]); a[3] = hmul2u(a[3], cs[ks*2+1]);
            #pragma unroll
            for (int j = 0; j < NJ; j++) mma16816(acc[mc][j], a, b[j]);
        }
    }

    // mask-free exp (pads are exp(0)=1; corrected in epilogue)
    #pragma unroll
    for (int mc = 0; mc < 2; mc++)
        #pragma unroll
        for (int j = 0; j < NJ; j++) {
            float e0 = __expf(acc[mc][j][0]), e1 = __expf(acc[mc][j][1]);
            float e2 = __expf(acc[mc][j][2]), e3 = __expf(acc[mc][j][3]);
            acc[mc][j][0] = e0; acc[mc][j][1] = e1;
            acc[mc][j][2] = e2; acc[mc][j][3] = e3;
            rowacc[mc*2]   += e0 + e1;
            rowacc[mc*2+1] += e2 + e3;
        }

    // col sums: shfl reduce over g, atomics from lanes 0..3
    #pragma unroll
    for (int j = 0; j < NJ; j++) {
        float c0 = acc[0][j][0] + acc[0][j][2] + acc[1][j][0] + acc[1][j][2];
        float c1 = acc[0][j][1] + acc[0][j][3] + acc[1][j][1] + acc[1][j][3];
        #pragma unroll
        for (int o = 4; o <= 16; o <<= 1) {
            c0 += __shfl_xor_sync(0xffffffffu, c0, o);
            c1 += __shfl_xor_sync(0xffffffffu, c1, o);
        }
        if (g == 0) {
            int cc = tbase + j*8 + 2*t4;
            atomicAdd(&cq[cc], c0);
            atomicAdd(&cq[cc + 1], c1);
        }
    }
}

// ---------------- trittention v9b: 3 CTAs/SM, NJ=2 tiles, 2x pipelined tile loop ----------------
__global__ __launch_bounds__(TT_THREADS, 3)
void tritt_mma_kernel(const float* __restrict__ abcde, float* __restrict__ Z) {
    extern __shared__ char smc[];
    float* redf  = (float*)(smc + SMB_RED);
    float* cvec4 = (float*)(smc + SMB_CVEC4);   // [4][64]
    float* rowm4 = (float*)(smc + SMB_ROWM4);   // [4][208]
    float* colm4 = (float*)(smc + SMB_COLM4);   // [4][208]
    uint32_t su = smem_u32(smc + SMB_A);
    uint32_t sb = smem_u32(smc + SMB_B);

    const int tid = threadIdx.x;
    const int warp = tid >> 5, lane = tid & 31;
    const int g = lane >> 2, t4 = lane & 3;

    int pair = blockIdx.x / NQCHUNK;
    int qc = blockIdx.x % NQCHUNK;
    int b = pair >> 2, h = pair & 3;
    const float* base = abcde + (size_t)b * TQ * FIVE;
    const int hoff = h * DH;
    int q0 = qc * QB;
    int nq = (TQ - q0 < QB) ? (TQ - q0) : QB;

    // ---- setup: A bf16 (224 rows, zero-padded), B bf16 (208 rows, zero-padded) ----
    for (int idx = tid; idx < MPAD*32; idx += TT_THREADS) {
        int s = idx >> 5, dp = (idx & 31) << 1;
        uint32_t val = 0u;
        if (s < TQ) {
            float2 av = *(const float2*)&base[(size_t)s*FIVE + hoff + dp];
            __nv_bfloat162 pp = __floats2bfloat162_rn(av.x, av.y);
            val = *(uint32_t*)&pp;
        }
        *(uint32_t*)(smc + SMB_A + swz((uint32_t)(s*128 + dp*2))) = val;
    }
    for (int idx = tid; idx < BROWS*32; idx += TT_THREADS) {
        int t = idx >> 5, dp = (idx & 31) << 1;
        uint32_t val = 0u;
        if (t < TQ) {
            float2 bv = *(const float2*)&base[(size_t)t*FIVE + DIMM + hoff + dp];
            __nv_bfloat162 pp = __floats2bfloat162_rn(bv.x, bv.y);
            val = *(uint32_t*)&pp;
        }
        *(uint32_t*)(smc + SMB_B + swz((uint32_t)(t*128 + dp*2))) = val;
    }
    {
        int qi = tid >> 6, d = tid & 63;
        cvec4[qi*64 + d] = (qi < nq)
            ? base[(size_t)(q0 + qi)*FIVE + 2*DIMM + hoff + d] * (1.0f/DH) : 0.f;
    }
    for (int i = tid; i < 4*BROWS; i += TT_THREADS) { rowm4[i] = 0.f; colm4[i] = 0.f; }
    __syncthreads();

    // ---- main loop: warps 0..6; q-OUTER (not unrolled), 13 NJ=2 tiles (2x pipelined) ----
    if (warp < 7) {
        #pragma unroll 1
        for (int iq = 0; iq < nq; iq++) {
            const float* cv = cvec4 + iq*64;
            uint32_t cs[8];
            #pragma unroll
            for (int ks = 0; ks < 4; ks++) {
                int k = ks*16 + 2*t4;
                __nv_bfloat162 p0 = __floats2bfloat162_rn(cv[k], cv[k+1]);
                __nv_bfloat162 p1 = __floats2bfloat162_rn(cv[k+8], cv[k+9]);
                cs[ks*2+0] = *(uint32_t*)&p0;
                cs[ks*2+1] = *(uint32_t*)&p1;
            }
            float rowacc[4] = {0.f, 0.f, 0.f, 0.f};
            float* cq = colm4 + iq*BROWS;

            #pragma unroll 2
            for (int tb = 0; tb < 208; tb += 16)
                tt_tile9<2>(tb, su, sb, cs, rowacc, cq, warp, lane);

            #pragma unroll
            for (int i = 0; i < 4; i++) {
                rowacc[i] += __shfl_xor_sync(0xffffffffu, rowacc[i], 1);
                rowacc[i] += __shfl_xor_sync(0xffffffffu, rowacc[i], 2);
            }
            if (t4 == 0) {
                float* rq = rowm4 + iq*BROWS;
                #pragma unroll
                for (int i = 0; i < 4; i++) {
                    int r = warp*32 + (i >> 1)*16 + (i & 1)*8 + g;
                    if (r < TQ) rq[r] = rowacc[i];
                }
            }
        }
    }
    __syncthreads();

    // ---- Z total per q (raw; corrected by -ZCORR) ----
    int qi = tid >> 6, d = tid & 63;
    {
        const float* rq = rowm4 + qi*BROWS;
        float part = rq[d] + rq[d + 64] + rq[d + 128] + ((d < 16) ? rq[d + 192] : 0.f);
        #pragma unroll
        for (int o = 16; o > 0; o >>= 1) part += __shfl_xor_sync(0xffffffffu, part, o);
        if (lane == 0) redf[warp] = part;
    }
    __syncthreads();

    // ---- batched epilogue with pad corrections ----
    if (qi < nq) {
        float inv = 1.f / (redf[qi*2] + redf[qi*2 + 1] - ZCORR);
        const float* rq = rowm4 + qi*BROWS;
        const float* cq = colm4 + qi*BROWS;
        const float* Dp = base + 3*DIMM + hoff + d;
        const float* Ep = base + 4*DIMM + hoff + d;
        float accz = 0.f;
        #pragma unroll 4
        for (int s = 0; s < TQ; s++) {
            accz += (rq[s] - PADC) * Dp[(size_t)s*FIVE];
            accz += (cq[s] - PADR) * Ep[(size_t)s*FIVE];
        }
        Z[((size_t)(b*TQ + q0 + qi))*DIMM + hoff + d] = accz * inv;
    }
}

// ---------------- classifier head (in-block K split; XN already final-LN'd) ----------------
__global__ void head_kernel(const float* __restrict__ XN, const float* __restrict__ W,
                            const float* __restrict__ bias, float* __restrict__ out) {
    __shared__ float sacc[256];
    int tid = threadIdx.x;
    int c = tid & 63, kc = tid >> 6;
    int n = blockIdx.x * 64 + c;
    int b = blockIdx.y;
    const float* x = XN + (size_t)b * TQ * DIMM;
    float acc = 0.f;
    if (n < NCLS) {
        #pragma unroll 8
        for (int i = 0; i < 64; i++) {
            int k = kc*64 + i;
            acc += x[k] * W[(size_t)k*NCLS + n];
        }
    }
    sacc[tid] = acc;
    __syncthreads();
    if (kc == 0 && n < NCLS)
        out[(size_t)b*NCLS + n] = sacc[c] + sacc[64 + c] + sacc[128 + c] + sacc[192 + c] + bias[n];
}

// ---------------- host launch ----------------
extern "C" void kernel_launch(void* const* d_in, const int* in_sizes, int n_in,
                              void* d_out, int out_size) {
    const float* img         = (const float*)d_in[0];
    const float* patch_ln1_g = (const float*)d_in[1];
    const float* patch_ln1_b = (const float*)d_in[2];
    const float* patch_w     = (const float*)d_in[3];
    const float* patch_b     = (const float*)d_in[4];
    const float* patch_ln2_g = (const float*)d_in[5];
    const float* patch_ln2_b = (const float*)d_in[6];
    const float* pos_emb     = (const float*)d_in[7];
    const float* cls_token   = (const float*)d_in[8];
    const float* attn_ln_g   = (const float*)d_in[9];
    const float* attn_ln_b   = (const float*)d_in[10];
    const float* w_abcde     = (const float*)d_in[11];
    const float* b_abcde     = (const float*)d_in[12];
    const float* w_out       = (const float*)d_in[13];
    const float* b_out       = (const float*)d_in[14];
    const float* ff_ln_g     = (const float*)d_in[15];
    const float* ff_ln_b     = (const float*)d_in[16];
    const float* ff_w1       = (const float*)d_in[17];
    const float* ff_b1       = (const float*)d_in[18];
    const float* ff_w2       = (const float*)d_in[19];
    const float* ff_b2       = (const float*)d_in[20];
    const float* final_ln_g  = (const float*)d_in[21];
    const float* final_ln_b  = (const float*)d_in[22];
    const float* head_w      = (const float*)d_in[23];
    const float* head_b      = (const float*)d_in[24];
    float* out = (float*)d_out;

    float *pn, *x, *xn, *ab, *z, *hb, *pp;
    cudaGetSymbolAddress((void**)&pn, g_pn);
    cudaGetSymbolAddress((void**)&x,  g_x);
    cudaGetSymbolAddress((void**)&xn, g_xn);
    cudaGetSymbolAddress((void**)&ab, g_ab);
    cudaGetSymbolAddress((void**)&z,  g_z);
    cudaGetSymbolAddress((void**)&hb, g_h);
    cudaGetSymbolAddress((void**)&pp, g_part);

    cudaFuncSetAttribute(tritt_mma_kernel,
                         cudaFuncAttributeMaxDynamicSharedMemorySize, SMB_TOTAL);

    // patch embed: gather+LN1, split-K GEMM, fused combine+LN2+pos+attnLN0
    gather_ln_kernel<<<BATCH*NPATCH, 256>>>(img, patch_ln1_g, patch_ln1_b);
    gemm_part_kernel<<<dim3(4, 7, 3), 256>>>(pn, patch_w, pp, BATCH*NPATCH, DIMM, 256);
    assemble_fused_kernel<<<MROWS, 256>>>(pp, patch_b, patch_ln2_g, patch_ln2_b,
                                          cls_token, pos_emb, attn_ln_g, attn_ln_b, x, xn);

    for (int L = 0; L < 2; L++) {
        gemm_kernel<0><<<dim3(20, 7), 256>>>(xn, w_abcde + (size_t)L*DIMM*FIVE,
                                             b_abcde + L*FIVE, nullptr, ab,
                                             MROWS, DIMM, FIVE);
        tritt_mma_kernel<<<BATCH*HEADS*NQCHUNK, TT_THREADS, SMB_TOTAL>>>(ab, z);
        // out proj: split-K 4 (klen=64), combine fused with ff LN
        gemm_part_kernel<<<dim3(4, 7, 4), 256>>>(z, w_out + (size_t)L*DIMM*DIMM,
                                                 pp, MROWS, DIMM, 64);
        combine_ln_kernel<<<MROWS, 256>>>(pp, 4, b_out + L*DIMM, x,
                                          ff_ln_g + L*DIMM, ff_ln_b + L*DIMM, x, xn);
        gemm_kernel<1><<<dim3(16, 7), 256>>>(xn, ff_w1 + (size_t)L*DIMM*MLPD,
                                             ff_b1 + L*MLPD, nullptr, hb,
                                             MROWS, DIMM, MLPD);
        gemm_part_kernel<<<dim3(4, 7, 4), 256>>>(hb, ff_w2 + (size_t)L*MLPD*DIMM,
                                                 pp, MROWS, DIMM, 256);
        const float* ng = (L == 0) ? (attn_ln_g + DIMM) : final_ln_g;
        const float* nb = (L == 0) ? (attn_ln_b + DIMM) : final_ln_b;
        combine_ln_kernel<<<MROWS, 256>>>(pp, 4, ff_b2 + L*DIMM, x, ng, nb, x, xn);
    }

    head_kernel<<<dim3(16, BATCH), 256>>>(xn, head_w, head_b, out);
}

// round 17
// speedup vs baseline: 1.6287x; 1.0561x over previous
#include <cuda_runtime.h>
#include <cuda_bf16.h>
#include <cstdint>
#include <math.h>

// ---------------- problem constants ----------------
#define BATCH     2
#define TQ        197
#define DIMM      256
#define HEADS     4
#define DH        64
#define FIVE      1280
#define MLPD      1024
#define NCLS      1000
#define PATCH_DIM 768
#define NPATCH    196
#define MROWS     (BATCH*TQ)     // 394

// ---------------- tritt v9 constants ----------------
#define TT_THREADS 256
#define MPAD       224           // 7 warps x 32 rows
#define BROWS      208
#define QB         4
#define NQCHUNK    50            // ceil(197/4)
#define PADC       11.0f         // pad cols per valid row (208-197)
#define PADR       27.0f         // pad rows per valid col (224-197)
#define ZCORR      (197.0f*PADC) // 2167

// dynamic smem byte offsets (A/B 1024-aligned for swizzle)
#define SMB_RED    0                        // 32 floats (8 used)
#define SMB_CVEC4  256                      // 4*64 floats
#define SMB_ROWM4  1280                     // 4*208 floats
#define SMB_COLM4  4608                     // 4*208 floats
#define SMB_A      8192                     // 224 x 128B bf16 swizzled
#define SMB_B      (SMB_A + MPAD*128)       // 36864: 208 x 128B
#define SMB_TOTAL  (SMB_B + BROWS*128)      // 63488 bytes

__device__ __forceinline__ uint32_t swz(uint32_t off) {
    return off ^ ((off >> 3) & 0x70);
}

// ---------------- device scratch ----------------
__device__ float g_pn[BATCH*NPATCH*PATCH_DIM];
__device__ float g_x[MROWS*DIMM];
__device__ float g_xn[MROWS*DIMM];
__device__ float g_ab[MROWS*FIVE];
__device__ float g_z[MROWS*DIMM];
__device__ float g_h[MROWS*MLPD];
__device__ float g_part[8*MROWS*DIMM];   // split-K partials (max 8 slabs)

// ---------------- PTX helpers ----------------
__device__ __forceinline__ uint32_t smem_u32(const void* p) {
    uint32_t a;
    asm("{ .reg .u64 t; cvta.to.shared.u64 t, %1; cvt.u32.u64 %0, t; }" : "=r"(a) : "l"(p));
    return a;
}
__device__ __forceinline__ void ldm_x4(uint32_t addr, uint32_t* r) {
    asm volatile("ldmatrix.sync.aligned.m8n8.x4.shared.b16 {%0,%1,%2,%3}, [%4];"
                 : "=r"(r[0]), "=r"(r[1]), "=r"(r[2]), "=r"(r[3]) : "r"(addr));
}
__device__ __forceinline__ void ldm_x2(uint32_t addr, uint32_t* r) {
    asm volatile("ldmatrix.sync.aligned.m8n8.x2.shared.b16 {%0,%1}, [%2];"
                 : "=r"(r[0]), "=r"(r[1]) : "r"(addr));
}
__device__ __forceinline__ void mma16816(float* c, const uint32_t* a, const uint32_t* b) {
    asm volatile("mma.sync.aligned.m16n8k16.row.col.f32.bf16.bf16.f32 "
                 "{%0,%1,%2,%3}, {%4,%5,%6,%7}, {%8,%9}, {%0,%1,%2,%3};"
                 : "+f"(c[0]), "+f"(c[1]), "+f"(c[2]), "+f"(c[3])
                 : "r"(a[0]), "r"(a[1]), "r"(a[2]), "r"(a[3]), "r"(b[0]), "r"(b[1]));
}
__device__ __forceinline__ uint32_t hmul2u(uint32_t a, uint32_t b) {
    __nv_bfloat162 x = *(__nv_bfloat162*)&a, y = *(__nv_bfloat162*)&b;
    __nv_bfloat162 z = __hmul2(x, y);
    return *(uint32_t*)&z;
}
// cp.async helpers (sm_80+ portable)
__device__ __forceinline__ void cp16(uint32_t smem, const void* g, bool pred) {
    int sz = pred ? 16 : 0;
    asm volatile("cp.async.cg.shared.global [%0], [%1], 16, %2;"
                 :: "r"(smem), "l"(g), "r"(sz));
}
__device__ __forceinline__ void cp_commit() {
    asm volatile("cp.async.commit_group;" ::: "memory");
}
template<int N>
__device__ __forceinline__ void cp_wait() {
    asm volatile("cp.async.wait_group %0;" :: "n"(N) : "memory");
}

// ---------------- reductions (blockDim == 256, 8 warps) ----------------
__device__ __forceinline__ float block_reduce_sum(float v, float* red) {
    #pragma unroll
    for (int o = 16; o > 0; o >>= 1) v += __shfl_xor_sync(0xffffffffu, v, o);
    if ((threadIdx.x & 31) == 0) red[threadIdx.x >> 5] = v;
    __syncthreads();
    if (threadIdx.x < 32) {
        float r = (threadIdx.x < 8) ? red[threadIdx.x] : 0.f;
        #pragma unroll
        for (int o = 4; o > 0; o >>= 1) r += __shfl_xor_sync(0xffffffffu, r, o);
        if (threadIdx.x == 0) red[0] = r;
    }
    __syncthreads();
    float out = red[0];
    __syncthreads();
    return out;
}

// ---------------- fused patch gather + LN1 ----------------
__global__ void gather_ln_kernel(const float* __restrict__ img,
                                 const float* __restrict__ g, const float* __restrict__ bv) {
    __shared__ float red[32];
    int row = blockIdx.x;
    int b = row / NPATCH, pidx = row % NPATCH;
    int gh = pidx / 14, gw = pidx % 14;
    float v[3];
    #pragma unroll
    for (int r = 0; r < 3; r++) {
        int j = threadIdx.x + r*256;
        int p1 = j / 48, rem = j % 48, p2 = rem / 3, c = rem % 3;
        v[r] = img[(((size_t)b*3 + c)*224 + gh*16 + p1)*224 + gw*16 + p2];
    }
    float s = v[0] + v[1] + v[2];
    float mean = block_reduce_sum(s, red) * (1.f/PATCH_DIM);
    float vs = 0.f;
    #pragma unroll
    for (int r = 0; r < 3; r++) { float d = v[r]-mean; vs += d*d; }
    float var = block_reduce_sum(vs, red) * (1.f/PATCH_DIM);
    float inv = rsqrtf(var + 1e-5f);
    #pragma unroll
    for (int r = 0; r < 3; r++) {
        int j = threadIdx.x + r*256;
        g_pn[(size_t)row*PATCH_DIM + j] = (v[r]-mean)*inv*g[j] + bv[j];
    }
}

// ---------------- fused assemble: patch combine (6 slabs) + LN2 + cls/pos + attn LN0 ----------------
__global__ void assemble_fused_kernel(const float* __restrict__ P,
                                      const float* __restrict__ pbias,
                                      const float* __restrict__ g2, const float* __restrict__ b2,
                                      const float* __restrict__ cls, const float* __restrict__ pos,
                                      const float* __restrict__ ga, const float* __restrict__ ba,
                                      float* __restrict__ X, float* __restrict__ XN) {
    __shared__ float red[32];
    int row = blockIdx.x;
    int b = row / TQ, t = row % TQ;
    int j = threadIdx.x;
    float xv;
    if (t == 0) {
        xv = cls[j] + pos[j];
    } else {
        int prow = b*NPATCH + t - 1;
        float v = pbias[j];
        #pragma unroll
        for (int s = 0; s < 6; s++)
            v += P[(size_t)s*BATCH*NPATCH*DIMM + (size_t)prow*DIMM + j];
        float mean = block_reduce_sum(v, red) * (1.f/DIMM);
        float d = v - mean;
        float var = block_reduce_sum(d*d, red) * (1.f/DIMM);
        float inv = rsqrtf(var + 1e-5f);
        xv = d*inv*g2[j] + b2[j] + pos[t*DIMM + j];
    }
    X[(size_t)row*DIMM + j] = xv;
    float mean = block_reduce_sum(xv, red) * (1.f/DIMM);
    float d = xv - mean;
    float var = block_reduce_sum(d*d, red) * (1.f/DIMM);
    float inv = rsqrtf(var + 1e-5f);
    XN[(size_t)row*DIMM + j] = d*inv*ga[j] + ba[j];
}

// ---------------- combine split-K + bias + residual -> X, then LN -> XN ----------------
__global__ void combine_ln_kernel(const float* __restrict__ P, int ns,
                                  const float* __restrict__ bias, const float* __restrict__ R,
                                  const float* __restrict__ g, const float* __restrict__ bv,
                                  float* __restrict__ X, float* __restrict__ XN) {
    __shared__ float red[32];
    int row = blockIdx.x;
    int j = threadIdx.x;
    float v = bias[j] + R[(size_t)row*DIMM + j];
    for (int s = 0; s < ns; s++)
        v += P[(size_t)s*MROWS*DIMM + (size_t)row*DIMM + j];
    X[(size_t)row*DIMM + j] = v;
    float mean = block_reduce_sum(v, red) * (1.f/DIMM);
    float d = v - mean;
    float var = block_reduce_sum(d*d, red) * (1.f/DIMM);
    float inv = rsqrtf(var + 1e-5f);
    XN[(size_t)row*DIMM + j] = d*inv*g[j] + bv[j];
}

// ---------------- fp32 GEMM 64x64 tile, cp.async double buffer ----------------
__device__ __forceinline__ float gelu_exact(float v) {
    return 0.5f * v * (1.f + erff(v * 0.70710678118654752f));
}

template<int ACT>
__global__ void gemm_kernel(const float* __restrict__ A, const float* __restrict__ W,
                            const float* __restrict__ bias, const float* __restrict__ R,
                            float* __restrict__ C, int M, int K, int N) {
    __shared__ float As[2][64][20];
    __shared__ float Ws[2][16][68];
    int tid = threadIdx.x;
    int tx = tid & 15, ty = tid >> 4;
    int m0 = blockIdx.y * 64, n0 = blockIdx.x * 64;
    float acc[4][4];
    #pragma unroll
    for (int i = 0; i < 4; i++)
        #pragma unroll
        for (int j = 0; j < 4; j++) acc[i][j] = 0.f;

    int am = tid >> 2, ak = (tid & 3) << 2;
    int wk = tid >> 4, wn4 = (tid & 15) << 2;
    bool arow_ok = (m0 + am < M);
    int nslabs = K >> 4;

    uint32_t sa0 = smem_u32(&As[0][am][ak]);
    uint32_t sa1 = smem_u32(&As[1][am][ak]);
    uint32_t sw0 = smem_u32(&Ws[0][wk][wn4]);
    uint32_t sw1 = smem_u32(&Ws[1][wk][wn4]);

    cp16(sa0, &A[(size_t)(m0 + am)*K + ak], arow_ok);
    cp16(sw0, &W[(size_t)wk*N + n0 + wn4], true);
    cp_commit();

    for (int s = 0; s < nslabs; s++) {
        int cur = s & 1;
        if (s + 1 < nslabs) {
            int k0 = (s + 1) << 4;
            cp16(cur ? sa0 : sa1, &A[(size_t)(m0 + am)*K + k0 + ak], arow_ok);
            cp16(cur ? sw0 : sw1, &W[(size_t)(k0 + wk)*N + n0 + wn4], true);
            cp_commit();
            cp_wait<1>();
        } else {
            cp_wait<0>();
        }
        __syncthreads();
        #pragma unroll
        for (int k = 0; k < 16; k++) {
            float a0 = As[cur][ty*4+0][k], a1 = As[cur][ty*4+1][k];
            float a2 = As[cur][ty*4+2][k], a3 = As[cur][ty*4+3][k];
            float w0 = Ws[cur][k][tx*4+0], w1 = Ws[cur][k][tx*4+1];
            float w2 = Ws[cur][k][tx*4+2], w3 = Ws[cur][k][tx*4+3];
            acc[0][0] += a0*w0; acc[0][1] += a0*w1; acc[0][2] += a0*w2; acc[0][3] += a0*w3;
            acc[1][0] += a1*w0; acc[1][1] += a1*w1; acc[1][2] += a1*w2; acc[1][3] += a1*w3;
            acc[2][0] += a2*w0; acc[2][1] += a2*w1; acc[2][2] += a2*w2; acc[2][3] += a2*w3;
            acc[3][0] += a3*w0; acc[3][1] += a3*w1; acc[3][2] += a3*w2; acc[3][3] += a3*w3;
        }
        __syncthreads();
    }
    #pragma unroll
    for (int i = 0; i < 4; i++) {
        int m = m0 + ty*4 + i;
        if (m >= M) continue;
        #pragma unroll
        for (int j = 0; j < 4; j++) {
            int n = n0 + tx*4 + j;
            float v = acc[i][j] + bias[n];
            if (ACT == 1) v = gelu_exact(v);
            if (R != nullptr) v += R[(size_t)m*N + n];
            C[(size_t)m*N + n] = v;
        }
    }
}

// ---------------- split-K fp32 GEMM with cp.async: partial slabs (64x64) ----------------
__global__ void gemm_part_kernel(const float* __restrict__ A, const float* __restrict__ W,
                                 float* __restrict__ P, int M, int N, int klen) {
    __shared__ float As[2][64][20];
    __shared__ float Ws[2][16][68];
    int tid = threadIdx.x;
    int tx = tid & 15, ty = tid >> 4;
    int m0 = blockIdx.y * 64, n0 = blockIdx.x * 64;
    int kstart = blockIdx.z * klen;
    int Kfull = klen * gridDim.z;
    float* C = P + (size_t)blockIdx.z * M * N;
    float acc[4][4];
    #pragma unroll
    for (int i = 0; i < 4; i++)
        #pragma unroll
        for (int j = 0; j < 4; j++) acc[i][j] = 0.f;

    int am = tid >> 2, ak = (tid & 3) << 2;
    int wk = tid >> 4, wn4 = (tid & 15) << 2;
    bool arow_ok = (m0 + am < M);
    int nslabs = klen >> 4;

    uint32_t sa0 = smem_u32(&As[0][am][ak]);
    uint32_t sa1 = smem_u32(&As[1][am][ak]);
    uint32_t sw0 = smem_u32(&Ws[0][wk][wn4]);
    uint32_t sw1 = smem_u32(&Ws[1][wk][wn4]);

    cp16(sa0, &A[(size_t)(m0 + am)*Kfull + kstart + ak], arow_ok);
    cp16(sw0, &W[(size_t)(kstart + wk)*N + n0 + wn4], true);
    cp_commit();

    for (int s = 0; s < nslabs; s++) {
        int cur = s & 1;
        if (s + 1 < nslabs) {
            int k0 = kstart + ((s + 1) << 4);
            cp16(cur ? sa0 : sa1, &A[(size_t)(m0 + am)*Kfull + k0 + ak], arow_ok);
            cp16(cur ? sw0 : sw1, &W[(size_t)(k0 + wk)*N + n0 + wn4], true);
            cp_commit();
            cp_wait<1>();
        } else {
            cp_wait<0>();
        }
        __syncthreads();
        #pragma unroll
        for (int k = 0; k < 16; k++) {
            float a0 = As[cur][ty*4+0][k], a1 = As[cur][ty*4+1][k];
            float a2 = As[cur][ty*4+2][k], a3 = As[cur][ty*4+3][k];
            float w0 = Ws[cur][k][tx*4+0], w1 = Ws[cur][k][tx*4+1];
            float w2 = Ws[cur][k][tx*4+2], w3 = Ws[cur][k][tx*4+3];
            acc[0][0] += a0*w0; acc[0][1] += a0*w1; acc[0][2] += a0*w2; acc[0][3] += a0*w3;
            acc[1][0] += a1*w0; acc[1][1] += a1*w1; acc[1][2] += a1*w2; acc[1][3] += a1*w3;
            acc[2][0] += a2*w0; acc[2][1] += a2*w1; acc[2][2] += a2*w2; acc[2][3] += a2*w3;
            acc[3][0] += a3*w0; acc[3][1] += a3*w1; acc[3][2] += a3*w2; acc[3][3] += a3*w3;
        }
        __syncthreads();
    }
    #pragma unroll
    for (int i = 0; i < 4; i++) {
        int m = m0 + ty*4 + i;
        if (m >= M) continue;
        #pragma unroll
        for (int j = 0; j < 4; j++) {
            int n = n0 + tx*4 + j;
            C[(size_t)m*N + n] = acc[i][j];
        }
    }
}

// ---------------- tritt v9 tile: NJ=2 (16 cols), minimal live set ----------------
template<int NJ>
__device__ __forceinline__ void tt_tile9(
    int tbase, uint32_t su, uint32_t sb, const uint32_t* cs,
    float* rowacc, float* cq, int warp, int lane)
{
    const int g = lane >> 2, t4 = lane & 3;
    const int l2 = lane & 15, brow = l2 & 7, bkb = (l2 >> 3) << 4;
    const int arow = (lane & 7) + ((lane >> 3) & 1) * 8, akb = (lane >> 4) << 4;

    float acc[2][NJ][4];
    #pragma unroll
    for (int mc = 0; mc < 2; mc++)
        #pragma unroll
        for (int j = 0; j < NJ; j++)
            #pragma unroll
            for (int r = 0; r < 4; r++) acc[mc][j][r] = 0.f;

    #pragma unroll
    for (int ks = 0; ks < 4; ks++) {
        uint32_t b[NJ][2];
        #pragma unroll
        for (int j = 0; j < NJ; j++)
            ldm_x2(sb + swz((uint32_t)((tbase + j*8 + brow)*128 + ks*32 + bkb)), b[j]);
        #pragma unroll
        for (int mc = 0; mc < 2; mc++) {
            uint32_t a[4];
            ldm_x4(su + swz((uint32_t)((warp*32 + mc*16 + arow)*128 + ks*32 + akb)), a);
            a[0] = hmul2u(a[0], cs[ks*2+0]); a[1] = hmul2u(a[1], cs[ks*2+0]);
            a[2] = hmul2u(a[2], cs[ks*2+1]); a[3] = hmul2u(a[3], cs[ks*2+1]);
            #pragma unroll
            for (int j = 0; j < NJ; j++) mma16816(acc[mc][j], a, b[j]);
        }
    }

    // mask-free exp (pads are exp(0)=1; corrected in epilogue)
    #pragma unroll
    for (int mc = 0; mc < 2; mc++)
        #pragma unroll
        for (int j = 0; j < NJ; j++) {
            float e0 = __expf(acc[mc][j][0]), e1 = __expf(acc[mc][j][1]);
            float e2 = __expf(acc[mc][j][2]), e3 = __expf(acc[mc][j][3]);
            acc[mc][j][0] = e0; acc[mc][j][1] = e1;
            acc[mc][j][2] = e2; acc[mc][j][3] = e3;
            rowacc[mc*2]   += e0 + e1;
            rowacc[mc*2+1] += e2 + e3;
        }

    // col sums: shfl reduce over g, atomics from lanes 0..3
    #pragma unroll
    for (int j = 0; j < NJ; j++) {
        float c0 = acc[0][j][0] + acc[0][j][2] + acc[1][j][0] + acc[1][j][2];
        float c1 = acc[0][j][1] + acc[0][j][3] + acc[1][j][1] + acc[1][j][3];
        #pragma unroll
        for (int o = 4; o <= 16; o <<= 1) {
            c0 += __shfl_xor_sync(0xffffffffu, c0, o);
            c1 += __shfl_xor_sync(0xffffffffu, c1, o);
        }
        if (g == 0) {
            int cc = tbase + j*8 + 2*t4;
            atomicAdd(&cq[cc], c0);
            atomicAdd(&cq[cc + 1], c1);
        }
    }
}

// ---------------- trittention v9c: 3 CTAs/SM, NJ=2 tiles, 4x pipelined tile loop ----------------
__global__ __launch_bounds__(TT_THREADS, 3)
void tritt_mma_kernel(const float* __restrict__ abcde, float* __restrict__ Z) {
    extern __shared__ char smc[];
    float* redf  = (float*)(smc + SMB_RED);
    float* cvec4 = (float*)(smc + SMB_CVEC4);   // [4][64]
    float* rowm4 = (float*)(smc + SMB_ROWM4);   // [4][208]
    float* colm4 = (float*)(smc + SMB_COLM4);   // [4][208]
    uint32_t su = smem_u32(smc + SMB_A);
    uint32_t sb = smem_u32(smc + SMB_B);

    const int tid = threadIdx.x;
    const int warp = tid >> 5, lane = tid & 31;
    const int g = lane >> 2, t4 = lane & 3;

    int pair = blockIdx.x / NQCHUNK;
    int qc = blockIdx.x % NQCHUNK;
    int b = pair >> 2, h = pair & 3;
    const float* base = abcde + (size_t)b * TQ * FIVE;
    const int hoff = h * DH;
    int q0 = qc * QB;
    int nq = (TQ - q0 < QB) ? (TQ - q0) : QB;

    // ---- setup: A bf16 (224 rows, zero-padded), B bf16 (208 rows, zero-padded) ----
    for (int idx = tid; idx < MPAD*32; idx += TT_THREADS) {
        int s = idx >> 5, dp = (idx & 31) << 1;
        uint32_t val = 0u;
        if (s < TQ) {
            float2 av = *(const float2*)&base[(size_t)s*FIVE + hoff + dp];
            __nv_bfloat162 pp = __floats2bfloat162_rn(av.x, av.y);
            val = *(uint32_t*)&pp;
        }
        *(uint32_t*)(smc + SMB_A + swz((uint32_t)(s*128 + dp*2))) = val;
    }
    for (int idx = tid; idx < BROWS*32; idx += TT_THREADS) {
        int t = idx >> 5, dp = (idx & 31) << 1;
        uint32_t val = 0u;
        if (t < TQ) {
            float2 bv = *(const float2*)&base[(size_t)t*FIVE + DIMM + hoff + dp];
            __nv_bfloat162 pp = __floats2bfloat162_rn(bv.x, bv.y);
            val = *(uint32_t*)&pp;
        }
        *(uint32_t*)(smc + SMB_B + swz((uint32_t)(t*128 + dp*2))) = val;
    }
    {
        int qi = tid >> 6, d = tid & 63;
        cvec4[qi*64 + d] = (qi < nq)
            ? base[(size_t)(q0 + qi)*FIVE + 2*DIMM + hoff + d] * (1.0f/DH) : 0.f;
    }
    for (int i = tid; i < 4*BROWS; i += TT_THREADS) { rowm4[i] = 0.f; colm4[i] = 0.f; }
    __syncthreads();

    // ---- main loop: warps 0..6; q-OUTER (not unrolled), 13 NJ=2 tiles (4x pipelined) ----
    if (warp < 7) {
        #pragma unroll 1
        for (int iq = 0; iq < nq; iq++) {
            const float* cv = cvec4 + iq*64;
            uint32_t cs[8];
            #pragma unroll
            for (int ks = 0; ks < 4; ks++) {
                int k = ks*16 + 2*t4;
                __nv_bfloat162 p0 = __floats2bfloat162_rn(cv[k], cv[k+1]);
                __nv_bfloat162 p1 = __floats2bfloat162_rn(cv[k+8], cv[k+9]);
                cs[ks*2+0] = *(uint32_t*)&p0;
                cs[ks*2+1] = *(uint32_t*)&p1;
            }
            float rowacc[4] = {0.f, 0.f, 0.f, 0.f};
            float* cq = colm4 + iq*BROWS;

            #pragma unroll 4
            for (int tb = 0; tb < 208; tb += 16)
                tt_tile9<2>(tb, su, sb, cs, rowacc, cq, warp, lane);

            #pragma unroll
            for (int i = 0; i < 4; i++) {
                rowacc[i] += __shfl_xor_sync(0xffffffffu, rowacc[i], 1);
                rowacc[i] += __shfl_xor_sync(0xffffffffu, rowacc[i], 2);
            }
            if (t4 == 0) {
                float* rq = rowm4 + iq*BROWS;
                #pragma unroll
                for (int i = 0; i < 4; i++) {
                    int r = warp*32 + (i >> 1)*16 + (i & 1)*8 + g;
                    if (r < TQ) rq[r] = rowacc[i];
                }
            }
        }
    }
    __syncthreads();

    // ---- Z total per q (raw; corrected by -ZCORR) ----
    int qi = tid >> 6, d = tid & 63;
    {
        const float* rq = rowm4 + qi*BROWS;
        float part = rq[d] + rq[d + 64] + rq[d + 128] + ((d < 16) ? rq[d + 192] : 0.f);
        #pragma unroll
        for (int o = 16; o > 0; o >>= 1) part += __shfl_xor_sync(0xffffffffu, part, o);
        if (lane == 0) redf[warp] = part;
    }
    __syncthreads();

    // ---- batched epilogue with pad corrections ----
    if (qi < nq) {
        float inv = 1.f / (redf[qi*2] + redf[qi*2 + 1] - ZCORR);
        const float* rq = rowm4 + qi*BROWS;
        const float* cq = colm4 + qi*BROWS;
        const float* Dp = base + 3*DIMM + hoff + d;
        const float* Ep = base + 4*DIMM + hoff + d;
        float accz = 0.f;
        #pragma unroll 4
        for (int s = 0; s < TQ; s++) {
            accz += (rq[s] - PADC) * Dp[(size_t)s*FIVE];
            accz += (cq[s] - PADR) * Ep[(size_t)s*FIVE];
        }
        Z[((size_t)(b*TQ + q0 + qi))*DIMM + hoff + d] = accz * inv;
    }
}

// ---------------- classifier head (in-block K split; XN already final-LN'd) ----------------
__global__ void head_kernel(const float* __restrict__ XN, const float* __restrict__ W,
                            const float* __restrict__ bias, float* __restrict__ out) {
    __shared__ float sacc[256];
    int tid = threadIdx.x;
    int c = tid & 63, kc = tid >> 6;
    int n = blockIdx.x * 64 + c;
    int b = blockIdx.y;
    const float* x = XN + (size_t)b * TQ * DIMM;
    float acc = 0.f;
    if (n < NCLS) {
        #pragma unroll 8
        for (int i = 0; i < 64; i++) {
            int k = kc*64 + i;
            acc += x[k] * W[(size_t)k*NCLS + n];
        }
    }
    sacc[tid] = acc;
    __syncthreads();
    if (kc == 0 && n < NCLS)
        out[(size_t)b*NCLS + n] = sacc[c] + sacc[64 + c] + sacc[128 + c] + sacc[192 + c] + bias[n];
}

// ---------------- host launch ----------------
extern "C" void kernel_launch(void* const* d_in, const int* in_sizes, int n_in,
                              void* d_out, int out_size) {
    const float* img         = (const float*)d_in[0];
    const float* patch_ln1_g = (const float*)d_in[1];
    const float* patch_ln1_b = (const float*)d_in[2];
    const float* patch_w     = (const float*)d_in[3];
    const float* patch_b     = (const float*)d_in[4];
    const float* patch_ln2_g = (const float*)d_in[5];
    const float* patch_ln2_b = (const float*)d_in[6];
    const float* pos_emb     = (const float*)d_in[7];
    const float* cls_token   = (const float*)d_in[8];
    const float* attn_ln_g   = (const float*)d_in[9];
    const float* attn_ln_b   = (const float*)d_in[10];
    const float* w_abcde     = (const float*)d_in[11];
    const float* b_abcde     = (const float*)d_in[12];
    const float* w_out       = (const float*)d_in[13];
    const float* b_out       = (const float*)d_in[14];
    const float* ff_ln_g     = (const float*)d_in[15];
    const float* ff_ln_b     = (const float*)d_in[16];
    const float* ff_w1       = (const float*)d_in[17];
    const float* ff_b1       = (const float*)d_in[18];
    const float* ff_w2       = (const float*)d_in[19];
    const float* ff_b2       = (const float*)d_in[20];
    const float* final_ln_g  = (const float*)d_in[21];
    const float* final_ln_b  = (const float*)d_in[22];
    const float* head_w      = (const float*)d_in[23];
    const float* head_b      = (const float*)d_in[24];
    float* out = (float*)d_out;

    float *pn, *x, *xn, *ab, *z, *hb, *pp;
    cudaGetSymbolAddress((void**)&pn, g_pn);
    cudaGetSymbolAddress((void**)&x,  g_x);
    cudaGetSymbolAddress((void**)&xn, g_xn);
    cudaGetSymbolAddress((void**)&ab, g_ab);
    cudaGetSymbolAddress((void**)&z,  g_z);
    cudaGetSymbolAddress((void**)&hb, g_h);
    cudaGetSymbolAddress((void**)&pp, g_part);

    cudaFuncSetAttribute(tritt_mma_kernel,
                         cudaFuncAttributeMaxDynamicSharedMemorySize, SMB_TOTAL);

    // patch embed: gather+LN1, split-K 6 GEMM, fused combine+LN2+pos+attnLN0
    gather_ln_kernel<<<BATCH*NPATCH, 256>>>(img, patch_ln1_g, patch_ln1_b);
    gemm_part_kernel<<<dim3(4, 7, 6), 256>>>(pn, patch_w, pp, BATCH*NPATCH, DIMM, 128);
    assemble_fused_kernel<<<MROWS, 256>>>(pp, patch_b, patch_ln2_g, patch_ln2_b,
                                          cls_token, pos_emb, attn_ln_g, attn_ln_b, x, xn);

    for (int L = 0; L < 2; L++) {
        gemm_kernel<0><<<dim3(20, 7), 256>>>(xn, w_abcde + (size_t)L*DIMM*FIVE,
                                             b_abcde + L*FIVE, nullptr, ab,
                                             MROWS, DIMM, FIVE);
        tritt_mma_kernel<<<BATCH*HEADS*NQCHUNK, TT_THREADS, SMB_TOTAL>>>(ab, z);
        // out proj: split-K 4 (klen=64), combine fused with ff LN
        gemm_part_kernel<<<dim3(4, 7, 4), 256>>>(z, w_out + (size_t)L*DIMM*DIMM,
                                                 pp, MROWS, DIMM, 64);
        combine_ln_kernel<<<MROWS, 256>>>(pp, 4, b_out + L*DIMM, x,
                                          ff_ln_g + L*DIMM, ff_ln_b + L*DIMM, x, xn);
        gemm_kernel<1><<<dim3(16, 7), 256>>>(xn, ff_w1 + (size_t)L*DIMM*MLPD,
                                             ff_b1 + L*MLPD, nullptr, hb,
                                             MROWS, DIMM, MLPD);
        // ff2: split-K 8 (klen=128)
        gemm_part_kernel<<<dim3(4, 7, 8), 256>>>(hb, ff_w2 + (size_t)L*MLPD*DIMM,
                                                 pp, MROWS, DIMM, 128);
        const float* ng = (L == 0) ? (attn_ln_g + DIMM) : final_ln_g;
        const float* nb = (L == 0) ? (attn_ln_b + DIMM) : final_ln_b;
        combine_ln_kernel<<<MROWS, 256>>>(pp, 8, ff_b2 + L*DIMM, x, ng, nb, x, xn);
    }

    head_kernel<<<dim3(16, BATCH), 256>>>(xn, head_w, head_b, out);
}